// round 8
// baseline (speedup 1.0000x reference)
#include <cuda_runtime.h>
#include <mma.h>
#include <math.h>
#include <stddef.h>
#include <stdint.h>

using namespace nvcuda;

static constexpr int CB  = 8;     // batch
static constexpr int CNQ = 1024;  // query tokens
static constexpr int CNK = 2048;  // key tokens
static constexpr int CD  = 1024;  // model dim
static constexpr int CH  = 8;     // heads
static constexpr int CDH = 128;   // head dim

// ---------------- scratch (no allocations allowed -> device globals) -------
__device__ float g_q[CB * CNQ * CD];   // q projection (fp32, exact for residual)
__device__ float g_k[CB * CNK * CD];   // k projection (tf32-rounded)
__device__ float g_v[CB * CNK * CD];   // v projection (tf32-rounded)
__device__ float g_x[CB * CNQ * CD];   // attn out / LN0 out
__device__ float g_y[CB * CNQ * CD];   // pre-LN1
__device__ float g_wr[4][CD * CD];     // tf32-rounded weights (row-major)
__device__ float g_qr[CB * CNQ * CD];  // tf32-rounded Q input
__device__ float g_kr[CB * CNK * CD];  // tf32-rounded K input
__device__ float g_xr[CB * CNQ * CD];  // tf32-rounded LN0 out

__device__ __forceinline__ float to_tf32(float x) {
    float r;
    asm("cvt.rna.tf32.f32 %0, %1;" : "=f"(r) : "f"(x));
    return r;
}

__device__ __forceinline__ uint32_t smem_u32(const void* p) {
    uint32_t a;
    asm("{ .reg .u64 t; cvta.to.shared.u64 t, %1; cvt.u32.u64 %0, t; }"
        : "=r"(a) : "l"(p));
    return a;
}

__device__ __forceinline__ void cpasync16(uint32_t dst, const float* src) {
    asm volatile("cp.async.cg.shared.global [%0], [%1], 16;"
                 :: "r"(dst), "l"(src));
}
#define CP_COMMIT() asm volatile("cp.async.commit_group;" ::: "memory")
#define CP_WAIT(n)  asm volatile("cp.async.wait_group %0;" :: "n"(n) : "memory")

typedef wmma::fragment<wmma::matrix_a, 16, 16, 8, wmma::precision::tf32, wmma::row_major> AFrag;
typedef wmma::fragment<wmma::matrix_b, 16, 16, 8, wmma::precision::tf32, wmma::row_major> BFragRow;
typedef wmma::fragment<wmma::matrix_b, 16, 16, 8, wmma::precision::tf32, wmma::col_major> BFragCol;
typedef wmma::fragment<wmma::accumulator, 16, 16, 8, float> CFrag;

// ===========================================================================
// 3-stage cp.async pipelined tf32 GEMM (proven in R7).
// relu_residual -> C = R + relu(A@W + bias); round_out -> store tf32-rounded.
// ===========================================================================
static constexpr int GS      = 3;
static constexpr int AS_LD   = 20;
static constexpr int BS_LD   = 132;
static constexpr int A_ST_F  = 128 * AS_LD;
static constexpr int STAGE_F = A_ST_F + 16 * BS_LD;
static constexpr int CS_LD   = 132;
static constexpr int GEMM_SMEM_BYTES = 128 * CS_LD * 4;

__global__ __launch_bounds__(256)
void gemm_pipe_kernel(const float* __restrict__ A, const float* __restrict__ W,
                      const float* __restrict__ bias, const float* __restrict__ R,
                      float* __restrict__ C, int relu_residual, int round_out)
{
    extern __shared__ float sm[];
    const int tid = threadIdx.x;
    const int w   = tid >> 5;
    const int wm  = w & 3;
    const int wn  = w >> 2;
    const int r0  = blockIdx.y * 128;
    const int n0  = blockIdx.x * 128;

    const int a_row = tid >> 1;
    const int a_c0  = (tid & 1) * 8;
    const int b_row = tid >> 4;
    const int b_c0  = (tid & 15) * 8;
    const float* Ap = A + (size_t)(r0 + a_row) * 1024 + a_c0;
    const float* Bp = W + (size_t)b_row * 1024 + n0 + b_c0;

    const uint32_t sbase = smem_u32(sm);
    const uint32_t as_dst = sbase + (a_row * AS_LD + a_c0) * 4;
    const uint32_t bs_dst = sbase + (A_ST_F + b_row * BS_LD + b_c0) * 4;

    CFrag acc[2][4];
#pragma unroll
    for (int i = 0; i < 2; ++i)
#pragma unroll
        for (int j = 0; j < 4; ++j) wmma::fill_fragment(acc[i][j], 0.f);

#pragma unroll
    for (int s = 0; s < GS - 1; ++s) {
        const uint32_t so = s * STAGE_F * 4;
        const float* ap = Ap + s * 16;
        const float* bp = Bp + (size_t)s * 16 * 1024;
        cpasync16(as_dst + so,      ap);
        cpasync16(as_dst + so + 16, ap + 4);
        cpasync16(bs_dst + so,      bp);
        cpasync16(bs_dst + so + 16, bp + 4);
        CP_COMMIT();
    }

    for (int kt = 0; kt < 64; ++kt) {
        CP_WAIT(1);
        __syncthreads();
        if (kt + 2 < 64) {
            const int s = (kt + 2) % GS;
            const uint32_t so = s * STAGE_F * 4;
            const float* ap = Ap + (kt + 2) * 16;
            const float* bp = Bp + (size_t)(kt + 2) * 16 * 1024;
            cpasync16(as_dst + so,      ap);
            cpasync16(as_dst + so + 16, ap + 4);
            cpasync16(bs_dst + so,      bp);
            cpasync16(bs_dst + so + 16, bp + 4);
        }
        CP_COMMIT();

        const float* As = sm + (kt % GS) * STAGE_F;
        const float* Bs = As + A_ST_F;
#pragma unroll
        for (int ks = 0; ks < 16; ks += 8) {
            AFrag af[2];
#pragma unroll
            for (int i = 0; i < 2; ++i)
                wmma::load_matrix_sync(af[i], &As[(wm * 32 + i * 16) * AS_LD + ks], AS_LD);
            BFragRow bf[4];
#pragma unroll
            for (int j = 0; j < 4; ++j)
                wmma::load_matrix_sync(bf[j], &Bs[ks * BS_LD + wn * 64 + j * 16], BS_LD);
#pragma unroll
            for (int i = 0; i < 2; ++i)
#pragma unroll
                for (int j = 0; j < 4; ++j)
                    wmma::mma_sync(acc[i][j], af[i], bf[j], acc[i][j]);
        }
    }

    CP_WAIT(0);
    __syncthreads();

    float* Cs = sm;
#pragma unroll
    for (int i = 0; i < 2; ++i)
#pragma unroll
        for (int j = 0; j < 4; ++j)
            wmma::store_matrix_sync(&Cs[(wm * 32 + i * 16) * CS_LD + wn * 64 + j * 16],
                                    acc[i][j], CS_LD, wmma::mem_row_major);
    __syncthreads();

    const int er  = tid >> 1;
    const int ec0 = (tid & 1) * 64;
#pragma unroll
    for (int qq = 0; qq < 16; ++qq) {
        const int c = ec0 + qq * 4;
        float4 bb = *(const float4*)(bias + n0 + c);
        const float* cp = &Cs[er * CS_LD + c];
        float4 val;
        val.x = cp[0] + bb.x; val.y = cp[1] + bb.y;
        val.z = cp[2] + bb.z; val.w = cp[3] + bb.w;
        if (relu_residual) {
            float4 rr = *(const float4*)(R + (size_t)(r0 + er) * 1024 + n0 + c);
            val.x = rr.x + fmaxf(val.x, 0.f);
            val.y = rr.y + fmaxf(val.y, 0.f);
            val.z = rr.z + fmaxf(val.z, 0.f);
            val.w = rr.w + fmaxf(val.w, 0.f);
        }
        if (round_out) {
            val.x = to_tf32(val.x); val.y = to_tf32(val.y);
            val.z = to_tf32(val.z); val.w = to_tf32(val.w);
        }
        *(float4*)(C + (size_t)(r0 + er) * 1024 + n0 + c) = val;
    }
}

// elementwise tf32 RNA rounding (float4)
__global__ __launch_bounds__(256)
void round_tf32_kernel(const float* __restrict__ in, float* __restrict__ out)
{
    const size_t i = (size_t)blockIdx.x * blockDim.x + threadIdx.x;
    float4 v = ((const float4*)in)[i];
    v.x = to_tf32(v.x); v.y = to_tf32(v.y);
    v.z = to_tf32(v.z); v.w = to_tf32(v.w);
    ((float4*)out)[i] = v;
}

// ===========================================================================
// Attention v2: 128-row Q tile, cp.async K/V streaming, tf32 wmma,
// no-max softmax. k/v arrive pre-rounded to tf32; q rounded at Qs load.
// smem: Qs[128][132] | Ks[64][132] | Vs[64][132] | Ps[128][68] | lrow[128]
// ===========================================================================
static constexpr int A_LD  = 132;
static constexpr int AP_LD = 68;
static constexpr int AQS_OFF = 0;
static constexpr int AKS_OFF = 128 * A_LD;                // 16896
static constexpr int AVS_OFF = AKS_OFF + 64 * A_LD;       // 25344
static constexpr int APS_OFF = AVS_OFF + 64 * A_LD;       // 33792
static constexpr int AL_OFF  = APS_OFF + 128 * AP_LD;     // 42496
static constexpr int ATT2_SMEM_BYTES = (AL_OFF + 128) * 4; // 170496

__device__ __forceinline__ void cp_tile64(uint32_t dst_base, const float* src, int tid)
{
#pragma unroll
    for (int u = 0; u < 8; ++u) {
        const int idx = tid + u * 256;     // 0..2047
        const int row = idx >> 5;          // 32 x 16B chunks per row
        const int c16 = idx & 31;
        cpasync16(dst_base + (uint32_t)(row * A_LD + c16 * 4) * 4,
                  src + (size_t)row * CD + c16 * 4);
    }
}

__global__ __launch_bounds__(256, 1)
void attn2_kernel(const float* __restrict__ q, const float* __restrict__ k,
                  const float* __restrict__ v, float* __restrict__ x)
{
    extern __shared__ float sm[];
    float* Qs   = sm + AQS_OFF;
    float* Ks   = sm + AKS_OFF;
    float* Vs   = sm + AVS_OFF;
    float* Ps   = sm + APS_OFF;
    float* lrow = sm + AL_OFF;

    const int b  = blockIdx.z;
    const int h  = blockIdx.y;
    const int q0 = blockIdx.x * 128;

    const float* qb = q + ((size_t)(b * CNQ + q0)) * CD + h * CDH;
    const float* kb = k + (size_t)b * CNK * CD + h * CDH;
    const float* vb = v + (size_t)b * CNK * CD + h * CDH;
    float*       xb = x + ((size_t)(b * CNQ + q0)) * CD + h * CDH;

    const int tid = threadIdx.x;
    const int w   = tid >> 5;
    const uint32_t ks_u = smem_u32(Ks);
    const uint32_t vs_u = smem_u32(Vs);

    // prefetch K tile 0
    cp_tile64(ks_u, kb, tid);
    CP_COMMIT();

    // load Q tile (tf32-rounded into smem)
    {
        const int r  = tid >> 1;
        const int c0 = (tid & 1) * 64;
#pragma unroll
        for (int u = 0; u < 16; ++u) {
            float4 vq = *(const float4*)(qb + (size_t)r * CD + c0 + u * 4);
            float* p = &Qs[r * A_LD + c0 + u * 4];
            p[0] = to_tf32(vq.x); p[1] = to_tf32(vq.y);
            p[2] = to_tf32(vq.z); p[3] = to_tf32(vq.w);
        }
        if (tid < 128) lrow[tid] = 0.f;
    }

    CFrag oacc[8];
#pragma unroll
    for (int j = 0; j < 8; ++j) wmma::fill_fragment(oacc[j], 0.f);

    const float scale = 0.03125f;   // 1/sqrt(1024)

    for (int kt = 0; kt < CNK / 64; ++kt) {
        CP_WAIT(0);          // K tile kt resident
        __syncthreads();     // + Qs visible (iter0), prev PV done with Vs

        // stream V tile kt while computing S
        cp_tile64(vs_u, vb + (size_t)(kt * 64) * CD, tid);
        CP_COMMIT();

        // ---- S = Q @ K^T : warp w -> rows w*16..+15, cols 0..63 ----
        {
            CFrag sacc[4];
#pragma unroll
            for (int j = 0; j < 4; ++j) wmma::fill_fragment(sacc[j], 0.f);
#pragma unroll
            for (int kk = 0; kk < 128; kk += 8) {
                AFrag af;
                wmma::load_matrix_sync(af, &Qs[(w * 16) * A_LD + kk], A_LD);
#pragma unroll
                for (int j = 0; j < 4; ++j) {
                    BFragCol bf;
                    wmma::load_matrix_sync(bf, &Ks[(j * 16) * A_LD + kk], A_LD);
                    wmma::mma_sync(sacc[j], af, bf, sacc[j]);
                }
            }
#pragma unroll
            for (int j = 0; j < 4; ++j)
                wmma::store_matrix_sync(&Ps[(w * 16) * AP_LD + j * 16],
                                        sacc[j], AP_LD, wmma::mem_row_major);
        }
        __syncthreads();     // Ps complete, Ks reads done

        // stream K tile kt+1 while exp + PV run
        const bool more = (kt + 1 < CNK / 64);
        if (more) {
            cp_tile64(ks_u, kb + (size_t)((kt + 1) * 64) * CD, tid);
            CP_COMMIT();
        }

        // ---- softmax piece: exp + row-sum (2 threads per row) ----
        {
            const int r  = tid >> 1;
            const int c0 = (tid & 1) * 32;
            float* pr = &Ps[r * AP_LD + c0];
            float sum = 0.f;
#pragma unroll
            for (int u = 0; u < 32; ++u) {
                float e = __expf(pr[u] * scale);
                sum += e;
                pr[u] = to_tf32(e);
            }
            sum += __shfl_xor_sync(0xffffffffu, sum, 1);
            if ((tid & 1) == 0) lrow[r] += sum;
        }

        if (more) CP_WAIT(1);   // V resident (K kt+1 may still be in flight)
        else      CP_WAIT(0);
        __syncthreads();

        // ---- O += P @ V : warp w -> rows w*16..+15, cols 0..127 ----
#pragma unroll
        for (int jj = 0; jj < 64; jj += 8) {
            AFrag af;
            wmma::load_matrix_sync(af, &Ps[(w * 16) * AP_LD + jj], AP_LD);
#pragma unroll
            for (int j = 0; j < 8; ++j) {
                BFragRow bf;
                wmma::load_matrix_sync(bf, &Vs[jj * A_LD + j * 16], A_LD);
                wmma::mma_sync(oacc[j], af, bf, oacc[j]);
            }
        }
    }

    // ---- epilogue: x = q(fp32) + O / l ----
    __syncthreads();
#pragma unroll
    for (int j = 0; j < 8; ++j)
        wmma::store_matrix_sync(&Qs[(w * 16) * A_LD + j * 16],
                                oacc[j], A_LD, wmma::mem_row_major);
    __syncthreads();
    {
        const int r  = tid >> 1;
        const int c0 = (tid & 1) * 64;
        const float inv = 1.f / lrow[r];
#pragma unroll
        for (int u = 0; u < 16; ++u) {
            const int c = c0 + u * 4;
            float4 qres = *(const float4*)(qb + (size_t)r * CD + c);
            const float* op = &Qs[r * A_LD + c];
            float4 ov;
            ov.x = fmaf(op[0], inv, qres.x);
            ov.y = fmaf(op[1], inv, qres.y);
            ov.z = fmaf(op[2], inv, qres.z);
            ov.w = fmaf(op[3], inv, qres.w);
            *(float4*)(xb + (size_t)r * CD + c) = ov;
        }
    }
}

// ===========================================================================
// Row LayerNorm over 1024 columns.
// ===========================================================================
__global__ __launch_bounds__(256)
void ln_kernel(const float* __restrict__ in, float* __restrict__ out,
               const float* __restrict__ g, const float* __restrict__ bta)
{
    __shared__ float red_s[8], red_s2[8];
    __shared__ float mu_s, rs_s;
    const int row = blockIdx.x;
    const int tid = threadIdx.x;
    const float* rp = in + (size_t)row * 1024;

    float4 xv = *(const float4*)(rp + tid * 4);
    float s  = xv.x + xv.y + xv.z + xv.w;
    float s2 = xv.x * xv.x + xv.y * xv.y + xv.z * xv.z + xv.w * xv.w;
#pragma unroll
    for (int off = 16; off >= 1; off >>= 1) {
        s  += __shfl_xor_sync(0xffffffffu, s,  off);
        s2 += __shfl_xor_sync(0xffffffffu, s2, off);
    }
    if ((tid & 31) == 0) { red_s[tid >> 5] = s; red_s2[tid >> 5] = s2; }
    __syncthreads();
    if (tid == 0) {
        float a = 0.f, a2 = 0.f;
#pragma unroll
        for (int wq = 0; wq < 8; ++wq) { a += red_s[wq]; a2 += red_s2[wq]; }
        const float mu  = a * (1.f / 1024.f);
        const float var = a2 * (1.f / 1024.f) - mu * mu;
        mu_s = mu;
        rs_s = rsqrtf(var + 1e-5f);
    }
    __syncthreads();
    const float mu = mu_s, rs = rs_s;
    float4 gv = *(const float4*)(g + tid * 4);
    float4 bv = *(const float4*)(bta + tid * 4);
    float4 ov;
    ov.x = (xv.x - mu) * rs * gv.x + bv.x;
    ov.y = (xv.y - mu) * rs * gv.y + bv.y;
    ov.z = (xv.z - mu) * rs * gv.z + bv.z;
    ov.w = (xv.w - mu) * rs * gv.w + bv.w;
    *(float4*)(out + (size_t)row * 1024 + tid * 4) = ov;
}

// ===========================================================================
extern "C" void kernel_launch(void* const* d_in, const int* in_sizes, int n_in,
                              void* d_out, int out_size)
{
    const float* Q  = (const float*)d_in[0];
    const float* K  = (const float*)d_in[1];
    const float* Wq = (const float*)d_in[2];
    const float* bq = (const float*)d_in[3];
    const float* Wk = (const float*)d_in[4];
    const float* bk = (const float*)d_in[5];
    const float* Wv = (const float*)d_in[6];
    const float* bv = (const float*)d_in[7];
    const float* Wo = (const float*)d_in[8];
    const float* bo = (const float*)d_in[9];
    const float* g0 = (const float*)d_in[10];
    const float* b0 = (const float*)d_in[11];
    const float* g1 = (const float*)d_in[12];
    const float* b1 = (const float*)d_in[13];
    float* out = (float*)d_out;

    float *qp, *kp, *vp, *xp, *yp, *wrp, *qrp, *krp, *xrp;
    cudaGetSymbolAddress((void**)&qp,  g_q);
    cudaGetSymbolAddress((void**)&kp,  g_k);
    cudaGetSymbolAddress((void**)&vp,  g_v);
    cudaGetSymbolAddress((void**)&xp,  g_x);
    cudaGetSymbolAddress((void**)&yp,  g_y);
    cudaGetSymbolAddress((void**)&wrp, g_wr);
    cudaGetSymbolAddress((void**)&qrp, g_qr);
    cudaGetSymbolAddress((void**)&krp, g_kr);
    cudaGetSymbolAddress((void**)&xrp, g_xr);

    cudaFuncSetAttribute(gemm_pipe_kernel,
                         cudaFuncAttributeMaxDynamicSharedMemorySize,
                         GEMM_SMEM_BYTES);
    cudaFuncSetAttribute(attn2_kernel,
                         cudaFuncAttributeMaxDynamicSharedMemorySize,
                         ATT2_SMEM_BYTES);

    // prep: tf32-round activations + weights
    round_tf32_kernel<<<CB * CNQ * CD / 1024, 256>>>(Q, qrp);
    round_tf32_kernel<<<CB * CNK * CD / 1024, 256>>>(K, krp);
    round_tf32_kernel<<<CD * CD / 1024, 256>>>(Wq, wrp + 0 * CD * CD);
    round_tf32_kernel<<<CD * CD / 1024, 256>>>(Wk, wrp + 1 * CD * CD);
    round_tf32_kernel<<<CD * CD / 1024, 256>>>(Wv, wrp + 2 * CD * CD);
    round_tf32_kernel<<<CD * CD / 1024, 256>>>(Wo, wrp + 3 * CD * CD);

    // projections: q exact fp32; k/v stored tf32-rounded (MMA-only consumers)
    gemm_pipe_kernel<<<dim3(8,  64), 256, GEMM_SMEM_BYTES>>>(qrp, wrp + 0 * CD * CD, bq, nullptr, qp, 0, 0);
    gemm_pipe_kernel<<<dim3(8, 128), 256, GEMM_SMEM_BYTES>>>(krp, wrp + 1 * CD * CD, bk, nullptr, kp, 0, 1);
    gemm_pipe_kernel<<<dim3(8, 128), 256, GEMM_SMEM_BYTES>>>(krp, wrp + 2 * CD * CD, bv, nullptr, vp, 0, 1);

    // attention + residual (128-row Q tiles, cp.async streaming)
    attn2_kernel<<<dim3(CNQ / 128, CH, CB), 256, ATT2_SMEM_BYTES>>>(qp, kp, vp, xp);
    // LN0 (in place)
    ln_kernel<<<CB * CNQ, 256>>>(xp, xp, g0, b0);
    // y = x + relu(x @ Wo + bo)
    round_tf32_kernel<<<CB * CNQ * CD / 1024, 256>>>(xp, xrp);
    gemm_pipe_kernel<<<dim3(8, 64), 256, GEMM_SMEM_BYTES>>>(xrp, wrp + 3 * CD * CD, bo, xp, yp, 1, 0);
    // LN1 -> out
    ln_kernel<<<CB * CNQ, 256>>>(yp, out, g1, b1);
}

// round 11
// speedup vs baseline: 1.4640x; 1.4640x over previous
#include <cuda_runtime.h>
#include <mma.h>
#include <math.h>
#include <stddef.h>
#include <stdint.h>

using namespace nvcuda;

static constexpr int CB  = 8;     // batch
static constexpr int CNQ = 1024;  // query tokens
static constexpr int CNK = 2048;  // key tokens
static constexpr int CD  = 1024;  // model dim
static constexpr int CH  = 8;     // heads
static constexpr int CDH = 128;   // head dim

// ---------------- scratch (no allocations allowed -> device globals) -------
__device__ float g_q[CB * CNQ * CD];   // q projection (fp32 exact, for residual)
__device__ float g_qa[CB * CNQ * CD];  // q projection tf32-rounded (attn operand)
__device__ float g_k[CB * CNK * CD];   // k projection (tf32-rounded)
__device__ float g_v[CB * CNK * CD];   // v projection (tf32-rounded)
__device__ float g_x[CB * CNQ * CD];   // attn out / LN0 out
__device__ float g_y[CB * CNQ * CD];   // pre-LN1
__device__ float g_wr[4][CD * CD];     // tf32-rounded weights (row-major)
__device__ float g_qr[CB * CNQ * CD];  // tf32-rounded Q input
__device__ float g_kr[CB * CNK * CD];  // tf32-rounded K input
__device__ float g_xr[CB * CNQ * CD];  // tf32-rounded LN0 out

__device__ __forceinline__ float to_tf32(float x) {
    float r;
    asm("cvt.rna.tf32.f32 %0, %1;" : "=f"(r) : "f"(x));
    return r;
}

__device__ __forceinline__ uint32_t smem_u32(const void* p) {
    uint32_t a;
    asm("{ .reg .u64 t; cvta.to.shared.u64 t, %1; cvt.u32.u64 %0, t; }"
        : "=r"(a) : "l"(p));
    return a;
}

__device__ __forceinline__ void cpasync16(uint32_t dst, const float* src) {
    asm volatile("cp.async.cg.shared.global [%0], [%1], 16;"
                 :: "r"(dst), "l"(src));
}
#define CP_COMMIT() asm volatile("cp.async.commit_group;" ::: "memory")
#define CP_WAIT(n)  asm volatile("cp.async.wait_group %0;" :: "n"(n) : "memory")

typedef wmma::fragment<wmma::matrix_a, 16, 16, 8, wmma::precision::tf32, wmma::row_major> AFrag;
typedef wmma::fragment<wmma::matrix_b, 16, 16, 8, wmma::precision::tf32, wmma::row_major> BFragRow;
typedef wmma::fragment<wmma::matrix_b, 16, 16, 8, wmma::precision::tf32, wmma::col_major> BFragCol;
typedef wmma::fragment<wmma::accumulator, 16, 16, 8, float> CFrag;

// ===========================================================================
// 3-stage cp.async pipelined tf32 GEMM (proven R7/R8).
// relu_residual -> C = R + relu(A@W + bias); round_out -> store tf32-rounded.
// ===========================================================================
static constexpr int GS      = 3;
static constexpr int AS_LD   = 20;
static constexpr int BS_LD   = 132;
static constexpr int A_ST_F  = 128 * AS_LD;
static constexpr int STAGE_F = A_ST_F + 16 * BS_LD;
static constexpr int CS_LD   = 132;
static constexpr int GEMM_SMEM_BYTES = 128 * CS_LD * 4;

__global__ __launch_bounds__(256)
void gemm_pipe_kernel(const float* __restrict__ A, const float* __restrict__ W,
                      const float* __restrict__ bias, const float* __restrict__ R,
                      float* __restrict__ C, int relu_residual, int round_out)
{
    extern __shared__ float sm[];
    const int tid = threadIdx.x;
    const int w   = tid >> 5;
    const int wm  = w & 3;
    const int wn  = w >> 2;
    const int r0  = blockIdx.y * 128;
    const int n0  = blockIdx.x * 128;

    const int a_row = tid >> 1;
    const int a_c0  = (tid & 1) * 8;
    const int b_row = tid >> 4;
    const int b_c0  = (tid & 15) * 8;
    const float* Ap = A + (size_t)(r0 + a_row) * 1024 + a_c0;
    const float* Bp = W + (size_t)b_row * 1024 + n0 + b_c0;

    const uint32_t sbase = smem_u32(sm);
    const uint32_t as_dst = sbase + (a_row * AS_LD + a_c0) * 4;
    const uint32_t bs_dst = sbase + (A_ST_F + b_row * BS_LD + b_c0) * 4;

    CFrag acc[2][4];
#pragma unroll
    for (int i = 0; i < 2; ++i)
#pragma unroll
        for (int j = 0; j < 4; ++j) wmma::fill_fragment(acc[i][j], 0.f);

#pragma unroll
    for (int s = 0; s < GS - 1; ++s) {
        const uint32_t so = s * STAGE_F * 4;
        const float* ap = Ap + s * 16;
        const float* bp = Bp + (size_t)s * 16 * 1024;
        cpasync16(as_dst + so,      ap);
        cpasync16(as_dst + so + 16, ap + 4);
        cpasync16(bs_dst + so,      bp);
        cpasync16(bs_dst + so + 16, bp + 4);
        CP_COMMIT();
    }

    for (int kt = 0; kt < 64; ++kt) {
        CP_WAIT(1);
        __syncthreads();
        if (kt + 2 < 64) {
            const int s = (kt + 2) % GS;
            const uint32_t so = s * STAGE_F * 4;
            const float* ap = Ap + (kt + 2) * 16;
            const float* bp = Bp + (size_t)(kt + 2) * 16 * 1024;
            cpasync16(as_dst + so,      ap);
            cpasync16(as_dst + so + 16, ap + 4);
            cpasync16(bs_dst + so,      bp);
            cpasync16(bs_dst + so + 16, bp + 4);
        }
        CP_COMMIT();

        const float* As = sm + (kt % GS) * STAGE_F;
        const float* Bs = As + A_ST_F;
#pragma unroll
        for (int ks = 0; ks < 16; ks += 8) {
            AFrag af[2];
#pragma unroll
            for (int i = 0; i < 2; ++i)
                wmma::load_matrix_sync(af[i], &As[(wm * 32 + i * 16) * AS_LD + ks], AS_LD);
            BFragRow bf[4];
#pragma unroll
            for (int j = 0; j < 4; ++j)
                wmma::load_matrix_sync(bf[j], &Bs[ks * BS_LD + wn * 64 + j * 16], BS_LD);
#pragma unroll
            for (int i = 0; i < 2; ++i)
#pragma unroll
                for (int j = 0; j < 4; ++j)
                    wmma::mma_sync(acc[i][j], af[i], bf[j], acc[i][j]);
        }
    }

    CP_WAIT(0);
    __syncthreads();

    float* Cs = sm;
#pragma unroll
    for (int i = 0; i < 2; ++i)
#pragma unroll
        for (int j = 0; j < 4; ++j)
            wmma::store_matrix_sync(&Cs[(wm * 32 + i * 16) * CS_LD + wn * 64 + j * 16],
                                    acc[i][j], CS_LD, wmma::mem_row_major);
    __syncthreads();

    const int er  = tid >> 1;
    const int ec0 = (tid & 1) * 64;
#pragma unroll
    for (int qq = 0; qq < 16; ++qq) {
        const int c = ec0 + qq * 4;
        float4 bb = *(const float4*)(bias + n0 + c);
        const float* cp = &Cs[er * CS_LD + c];
        float4 val;
        val.x = cp[0] + bb.x; val.y = cp[1] + bb.y;
        val.z = cp[2] + bb.z; val.w = cp[3] + bb.w;
        if (relu_residual) {
            float4 rr = *(const float4*)(R + (size_t)(r0 + er) * 1024 + n0 + c);
            val.x = rr.x + fmaxf(val.x, 0.f);
            val.y = rr.y + fmaxf(val.y, 0.f);
            val.z = rr.z + fmaxf(val.z, 0.f);
            val.w = rr.w + fmaxf(val.w, 0.f);
        }
        if (round_out) {
            val.x = to_tf32(val.x); val.y = to_tf32(val.y);
            val.z = to_tf32(val.z); val.w = to_tf32(val.w);
        }
        *(float4*)(C + (size_t)(r0 + er) * 1024 + n0 + c) = val;
    }
}

// elementwise tf32 RNA rounding (float4)
__global__ __launch_bounds__(256)
void round_tf32_kernel(const float* __restrict__ in, float* __restrict__ out)
{
    const size_t i = (size_t)blockIdx.x * blockDim.x + threadIdx.x;
    float4 v = ((const float4*)in)[i];
    v.x = to_tf32(v.x); v.y = to_tf32(v.y);
    v.z = to_tf32(v.z); v.w = to_tf32(v.w);
    ((float4*)out)[i] = v;
}

// ===========================================================================
// Attention v3 (fixed): 64-row Q tile (occ 2), all loads cp.async (operands
// pre-rounded in gmem), K prefetch + V half-tiles, no-max softmax.
// smem: Qs[64][132] | Ks[64][132] | Vs[32][132] | Ps[64][68] | lrow[64]
// ===========================================================================
static constexpr int A_LD  = 132;
static constexpr int P_LD  = 68;                        // multiple of 4 (wmma ldm!)
static constexpr int AQS_OFF = 0;                       // 8448 f
static constexpr int AKS_OFF = 64 * A_LD;               // 8448 f
static constexpr int AVS_OFF = AKS_OFF + 64 * A_LD;     // +4224 f
static constexpr int APS_OFF = AVS_OFF + 32 * A_LD;     // +4352 f
static constexpr int ALR_OFF = APS_OFF + 64 * P_LD;     // +64 f
static constexpr int ATT_SMEM_F = ALR_OFF + 64;         // 25536 f
static constexpr int ATT3_SMEM_BYTES = ATT_SMEM_F * 4;  // 102144 B -> occ 2

// copy rows x 128 floats, gmem row stride CD, smem row stride A_LD
__device__ __forceinline__ void cp_rows(uint32_t dst_base, const float* src,
                                        int tid, int nchunks)
{
    for (int idx = tid; idx < nchunks; idx += 256) {
        const int row = idx >> 5;          // 32 x 16B chunks per row
        const int c16 = idx & 31;
        cpasync16(dst_base + (uint32_t)(row * A_LD + c16 * 4) * 4,
                  src + (size_t)row * CD + c16 * 4);
    }
}

__global__ __launch_bounds__(256, 2)
void attn3_kernel(const float* __restrict__ qa, const float* __restrict__ qe,
                  const float* __restrict__ k,  const float* __restrict__ v,
                  float* __restrict__ x)
{
    extern __shared__ float sm[];
    float* Qs   = sm + AQS_OFF;
    float* Ks   = sm + AKS_OFF;
    float* Vs   = sm + AVS_OFF;
    float* Ps   = sm + APS_OFF;
    float* lrow = sm + ALR_OFF;

    const int b  = blockIdx.z;
    const int h  = blockIdx.y;
    const int q0 = blockIdx.x * 64;

    const float* qab = qa + ((size_t)(b * CNQ + q0)) * CD + h * CDH;
    const float* qeb = qe + ((size_t)(b * CNQ + q0)) * CD + h * CDH;
    const float* kb  = k  + (size_t)b * CNK * CD + h * CDH;
    const float* vb  = v  + (size_t)b * CNK * CD + h * CDH;
    float*       xb  = x  + ((size_t)(b * CNQ + q0)) * CD + h * CDH;

    const int tid = threadIdx.x;
    const int w   = tid >> 5;
    const int wr  = w & 3;     // 16-row group
    const int wc  = w >> 2;    // col group
    const uint32_t qs_u = smem_u32(Qs);
    const uint32_t ks_u = smem_u32(Ks);
    const uint32_t vs_u = smem_u32(Vs);

    // prologue: Q | K0 | V0-half0 as three cp.async groups
    cp_rows(qs_u, qab, tid, 2048); CP_COMMIT();                 // [Q]
    cp_rows(ks_u, kb, tid, 2048);  CP_COMMIT();                 // [Q,K0]
    cp_rows(vs_u, vb, tid, 1024);  CP_COMMIT();                 // [Q,K0,V00]

    if (tid < 64) lrow[tid] = 0.f;

    CFrag oacc[4];
#pragma unroll
    for (int j = 0; j < 4; ++j) wmma::fill_fragment(oacc[j], 0.f);

    const float scale = 0.03125f;   // 1/sqrt(1024)

    CP_WAIT(1);          // Q, K0 resident; V00 may fly
    __syncthreads();

    for (int kt = 0; kt < CNK / 64; ++kt) {
        // ---- S = Q @ K^T : warp (wr, wc) -> rows wr*16, cols wc*32 ----
        CFrag sacc[2];
        wmma::fill_fragment(sacc[0], 0.f);
        wmma::fill_fragment(sacc[1], 0.f);
#pragma unroll
        for (int kk = 0; kk < 128; kk += 8) {
            AFrag af;
            wmma::load_matrix_sync(af, &Qs[(wr * 16) * A_LD + kk], A_LD);
#pragma unroll
            for (int j = 0; j < 2; ++j) {
                BFragCol bf;
                wmma::load_matrix_sync(bf, &Ks[(wc * 32 + j * 16) * A_LD + kk], A_LD);
                wmma::mma_sync(sacc[j], af, bf, sacc[j]);
            }
        }
        __syncthreads();                       // [1] S done: Ks free

        // prefetch K_{kt+1} (lands during exp + PV0)
        if (kt + 1 < CNK / 64) cp_rows(ks_u, kb + (size_t)((kt + 1) * 64) * CD, tid, 2048);
        CP_COMMIT();                           // pending: [Vh0, K']

#pragma unroll
        for (int j = 0; j < 2; ++j)
            wmma::store_matrix_sync(&Ps[(wr * 16) * P_LD + wc * 32 + j * 16],
                                    sacc[j], P_LD, wmma::mem_row_major);

        CP_WAIT(1);                            // Vh0 resident (K' flying)
        __syncthreads();                       // [2] Ps + Vs visible

        // ---- exp + row-sum: 4 threads per row, 16 vals each ----
        {
            const int r  = tid >> 2;
            const int c0 = (tid & 3) * 16;
            float* pr = &Ps[r * P_LD + c0];
            float sum = 0.f;
#pragma unroll
            for (int u = 0; u < 16; ++u) {
                float e = __expf(pr[u] * scale);
                sum += e;
                pr[u] = to_tf32(e);
            }
            sum += __shfl_xor_sync(0xffffffffu, sum, 1);
            sum += __shfl_xor_sync(0xffffffffu, sum, 2);
            if ((tid & 3) == 0) lrow[r] += sum;
        }
        __syncthreads();                       // [3] exp'd P visible

        // ---- PV half 0: O += P[:,0:32] @ V[0:32] ----
#pragma unroll
        for (int jj = 0; jj < 32; jj += 8) {
            AFrag af;
            wmma::load_matrix_sync(af, &Ps[(wr * 16) * P_LD + jj], P_LD);
#pragma unroll
            for (int j = 0; j < 4; ++j) {
                BFragRow bf;
                wmma::load_matrix_sync(bf, &Vs[jj * A_LD + wc * 64 + j * 16], A_LD);
                wmma::mma_sync(oacc[j], af, bf, oacc[j]);
            }
        }
        __syncthreads();                       // [4] Vs free

        // V half 1 (exposed ~one L2 latency)
        cp_rows(vs_u, vb + (size_t)(kt * 64 + 32) * CD, tid, 1024);
        CP_COMMIT();                           // pending: [K', Vh1]
        CP_WAIT(0);                            // K' + Vh1 resident
        __syncthreads();                       // [5]

        // ---- PV half 1: O += P[:,32:64] @ V[32:64] ----
#pragma unroll
        for (int jj = 0; jj < 32; jj += 8) {
            AFrag af;
            wmma::load_matrix_sync(af, &Ps[(wr * 16) * P_LD + 32 + jj], P_LD);
#pragma unroll
            for (int j = 0; j < 4; ++j) {
                BFragRow bf;
                wmma::load_matrix_sync(bf, &Vs[jj * A_LD + wc * 64 + j * 16], A_LD);
                wmma::mma_sync(oacc[j], af, bf, oacc[j]);
            }
        }
        __syncthreads();                       // [6] Vs free for next Vh0

        // prefetch V_{kt+1} half 0 (lands during next S)
        if (kt + 1 < CNK / 64) cp_rows(vs_u, vb + (size_t)((kt + 1) * 64) * CD, tid, 1024);
        CP_COMMIT();                           // pending: [Vh0']
    }

    // ---- epilogue: x = q_exact + O / l  (stage O in Qs) ----
    __syncthreads();
#pragma unroll
    for (int j = 0; j < 4; ++j)
        wmma::store_matrix_sync(&Qs[(wr * 16) * A_LD + wc * 64 + j * 16],
                                oacc[j], A_LD, wmma::mem_row_major);
    __syncthreads();
    {
        const int r  = tid >> 2;
        const int c0 = (tid & 3) * 32;
        const float inv = 1.f / lrow[r];
#pragma unroll
        for (int u = 0; u < 8; ++u) {
            const int c = c0 + u * 4;
            float4 qres = *(const float4*)(qeb + (size_t)r * CD + c);
            const float* op = &Qs[r * A_LD + c];
            float4 ov;
            ov.x = fmaf(op[0], inv, qres.x);
            ov.y = fmaf(op[1], inv, qres.y);
            ov.z = fmaf(op[2], inv, qres.z);
            ov.w = fmaf(op[3], inv, qres.w);
            *(float4*)(xb + (size_t)r * CD + c) = ov;
        }
    }
}

// ===========================================================================
// Row LayerNorm over 1024 columns.
// ===========================================================================
__global__ __launch_bounds__(256)
void ln_kernel(const float* __restrict__ in, float* __restrict__ out,
               const float* __restrict__ g, const float* __restrict__ bta)
{
    __shared__ float red_s[8], red_s2[8];
    __shared__ float mu_s, rs_s;
    const int row = blockIdx.x;
    const int tid = threadIdx.x;
    const float* rp = in + (size_t)row * 1024;

    float4 xv = *(const float4*)(rp + tid * 4);
    float s  = xv.x + xv.y + xv.z + xv.w;
    float s2 = xv.x * xv.x + xv.y * xv.y + xv.z * xv.z + xv.w * xv.w;
#pragma unroll
    for (int off = 16; off >= 1; off >>= 1) {
        s  += __shfl_xor_sync(0xffffffffu, s,  off);
        s2 += __shfl_xor_sync(0xffffffffu, s2, off);
    }
    if ((tid & 31) == 0) { red_s[tid >> 5] = s; red_s2[tid >> 5] = s2; }
    __syncthreads();
    if (tid == 0) {
        float a = 0.f, a2 = 0.f;
#pragma unroll
        for (int wq = 0; wq < 8; ++wq) { a += red_s[wq]; a2 += red_s2[wq]; }
        const float mu  = a * (1.f / 1024.f);
        const float var = a2 * (1.f / 1024.f) - mu * mu;
        mu_s = mu;
        rs_s = rsqrtf(var + 1e-5f);
    }
    __syncthreads();
    const float mu = mu_s, rs = rs_s;
    float4 gv = *(const float4*)(g + tid * 4);
    float4 bv = *(const float4*)(bta + tid * 4);
    float4 ov;
    ov.x = (xv.x - mu) * rs * gv.x + bv.x;
    ov.y = (xv.y - mu) * rs * gv.y + bv.y;
    ov.z = (xv.z - mu) * rs * gv.z + bv.z;
    ov.w = (xv.w - mu) * rs * gv.w + bv.w;
    *(float4*)(out + (size_t)row * 1024 + tid * 4) = ov;
}

// ===========================================================================
extern "C" void kernel_launch(void* const* d_in, const int* in_sizes, int n_in,
                              void* d_out, int out_size)
{
    const float* Q  = (const float*)d_in[0];
    const float* K  = (const float*)d_in[1];
    const float* Wq = (const float*)d_in[2];
    const float* bq = (const float*)d_in[3];
    const float* Wk = (const float*)d_in[4];
    const float* bk = (const float*)d_in[5];
    const float* Wv = (const float*)d_in[6];
    const float* bv = (const float*)d_in[7];
    const float* Wo = (const float*)d_in[8];
    const float* bo = (const float*)d_in[9];
    const float* g0 = (const float*)d_in[10];
    const float* b0 = (const float*)d_in[11];
    const float* g1 = (const float*)d_in[12];
    const float* b1 = (const float*)d_in[13];
    float* out = (float*)d_out;

    float *qp, *qap, *kp, *vp, *xp, *yp, *wrp, *qrp, *krp, *xrp;
    cudaGetSymbolAddress((void**)&qp,  g_q);
    cudaGetSymbolAddress((void**)&qap, g_qa);
    cudaGetSymbolAddress((void**)&kp,  g_k);
    cudaGetSymbolAddress((void**)&vp,  g_v);
    cudaGetSymbolAddress((void**)&xp,  g_x);
    cudaGetSymbolAddress((void**)&yp,  g_y);
    cudaGetSymbolAddress((void**)&wrp, g_wr);
    cudaGetSymbolAddress((void**)&qrp, g_qr);
    cudaGetSymbolAddress((void**)&krp, g_kr);
    cudaGetSymbolAddress((void**)&xrp, g_xr);

    cudaFuncSetAttribute(gemm_pipe_kernel,
                         cudaFuncAttributeMaxDynamicSharedMemorySize,
                         GEMM_SMEM_BYTES);
    cudaFuncSetAttribute(attn3_kernel,
                         cudaFuncAttributeMaxDynamicSharedMemorySize,
                         ATT3_SMEM_BYTES);

    // prep: tf32-round activations + weights
    round_tf32_kernel<<<CB * CNQ * CD / 1024, 256>>>(Q, qrp);
    round_tf32_kernel<<<CB * CNK * CD / 1024, 256>>>(K, krp);
    round_tf32_kernel<<<CD * CD / 1024, 256>>>(Wq, wrp + 0 * CD * CD);
    round_tf32_kernel<<<CD * CD / 1024, 256>>>(Wk, wrp + 1 * CD * CD);
    round_tf32_kernel<<<CD * CD / 1024, 256>>>(Wv, wrp + 2 * CD * CD);
    round_tf32_kernel<<<CD * CD / 1024, 256>>>(Wo, wrp + 3 * CD * CD);

    // projections: q exact fp32 (+ rounded copy); k/v stored tf32-rounded
    gemm_pipe_kernel<<<dim3(8,  64), 256, GEMM_SMEM_BYTES>>>(qrp, wrp + 0 * CD * CD, bq, nullptr, qp, 0, 0);
    gemm_pipe_kernel<<<dim3(8, 128), 256, GEMM_SMEM_BYTES>>>(krp, wrp + 1 * CD * CD, bk, nullptr, kp, 0, 1);
    gemm_pipe_kernel<<<dim3(8, 128), 256, GEMM_SMEM_BYTES>>>(krp, wrp + 2 * CD * CD, bv, nullptr, vp, 0, 1);
    round_tf32_kernel<<<CB * CNQ * CD / 1024, 256>>>(qp, qap);

    // attention + residual (64-row Q tiles, occ 2, async K/V pipeline)
    attn3_kernel<<<dim3(CNQ / 64, CH, CB), 256, ATT3_SMEM_BYTES>>>(qap, qp, kp, vp, xp);
    // LN0 (in place)
    ln_kernel<<<CB * CNQ, 256>>>(xp, xp, g0, b0);
    // y = x + relu(x @ Wo + bo)
    round_tf32_kernel<<<CB * CNQ * CD / 1024, 256>>>(xp, xrp);
    gemm_pipe_kernel<<<dim3(8, 64), 256, GEMM_SMEM_BYTES>>>(xrp, wrp + 3 * CD * CD, bo, xp, yp, 1, 0);
    // LN1 -> out
    ln_kernel<<<CB * CNQ, 256>>>(yp, out, g1, b1);
}

// round 12
// speedup vs baseline: 2.0838x; 1.4234x over previous
#include <cuda_runtime.h>
#include <mma.h>
#include <math.h>
#include <stddef.h>
#include <stdint.h>

using namespace nvcuda;

static constexpr int CB  = 8;     // batch
static constexpr int CNQ = 1024;  // query tokens
static constexpr int CNK = 2048;  // key tokens
static constexpr int CD  = 1024;  // model dim
static constexpr int CH  = 8;     // heads
static constexpr int CDH = 128;   // head dim

// ---------------- scratch (no allocations allowed -> device globals) -------
__device__ float g_q[CB * CNQ * CD];   // q projection (fp32 exact, residual)
__device__ float g_qa[CB * CNQ * CD];  // q packed (S A-fragment layout, rounded)
__device__ float g_k[CB * CNK * CD];   // k projection (tf32-rounded, row-major)
__device__ float g_v[CB * CNK * CD];   // v projection (tf32-rounded, row-major)
__device__ float g_k2[CB * CNK * CD];  // k packed (S B-fragment layout)
__device__ float g_v2[CB * CNK * CD];  // v packed (PV B-fragment layout)
__device__ float g_x[CB * CNQ * CD];   // attn out / LN0 out
__device__ float g_y[CB * CNQ * CD];   // pre-LN1
__device__ float g_wr[4][CD * CD];     // tf32-rounded weights (row-major)
__device__ float g_qr[CB * CNQ * CD];  // tf32-rounded Q input
__device__ float g_kr[CB * CNK * CD];  // tf32-rounded K input
__device__ float g_xr[CB * CNQ * CD];  // tf32-rounded LN0 out

__device__ __forceinline__ float to_tf32(float x) {
    float r;
    asm("cvt.rna.tf32.f32 %0, %1;" : "=f"(r) : "f"(x));
    return r;
}

__device__ __forceinline__ uint32_t smem_u32(const void* p) {
    uint32_t a;
    asm("{ .reg .u64 t; cvta.to.shared.u64 t, %1; cvt.u32.u64 %0, t; }"
        : "=r"(a) : "l"(p));
    return a;
}

__device__ __forceinline__ void cpasync16(uint32_t dst, const float* src) {
    asm volatile("cp.async.cg.shared.global [%0], [%1], 16;"
                 :: "r"(dst), "l"(src));
}
#define CP_COMMIT() asm volatile("cp.async.commit_group;" ::: "memory")
#define CP_WAIT(n)  asm volatile("cp.async.wait_group %0;" :: "n"(n) : "memory")

// raw tf32 mma: D(16x8) += A(16x8) * B(8x8);  A row-major, B col-major
__device__ __forceinline__ void mma1688(float* c, float4 a, float b0, float b1) {
    asm volatile(
        "mma.sync.aligned.m16n8k8.row.col.f32.tf32.tf32.f32 "
        "{%0,%1,%2,%3}, {%4,%5,%6,%7}, {%8,%9}, {%0,%1,%2,%3};"
        : "+f"(c[0]), "+f"(c[1]), "+f"(c[2]), "+f"(c[3])
        : "r"(__float_as_uint(a.x)), "r"(__float_as_uint(a.y)),
          "r"(__float_as_uint(a.z)), "r"(__float_as_uint(a.w)),
          "r"(__float_as_uint(b0)), "r"(__float_as_uint(b1)));
}

typedef wmma::fragment<wmma::matrix_a, 16, 16, 8, wmma::precision::tf32, wmma::row_major> AFrag;
typedef wmma::fragment<wmma::matrix_b, 16, 16, 8, wmma::precision::tf32, wmma::row_major> BFragRow;
typedef wmma::fragment<wmma::accumulator, 16, 16, 8, float> CFrag;

// ===========================================================================
// 3-stage cp.async pipelined tf32 GEMM (proven R7/R8/R11). Unchanged.
// ===========================================================================
static constexpr int GS      = 3;
static constexpr int AS_LD   = 20;
static constexpr int BS_LD   = 132;
static constexpr int A_ST_F  = 128 * AS_LD;
static constexpr int STAGE_F = A_ST_F + 16 * BS_LD;
static constexpr int CS_LD   = 132;
static constexpr int GEMM_SMEM_BYTES = 128 * CS_LD * 4;

__global__ __launch_bounds__(256)
void gemm_pipe_kernel(const float* __restrict__ A, const float* __restrict__ W,
                      const float* __restrict__ bias, const float* __restrict__ R,
                      float* __restrict__ C, int relu_residual, int round_out)
{
    extern __shared__ float sm[];
    const int tid = threadIdx.x;
    const int w   = tid >> 5;
    const int wm  = w & 3;
    const int wn  = w >> 2;
    const int r0  = blockIdx.y * 128;
    const int n0  = blockIdx.x * 128;

    const int a_row = tid >> 1;
    const int a_c0  = (tid & 1) * 8;
    const int b_row = tid >> 4;
    const int b_c0  = (tid & 15) * 8;
    const float* Ap = A + (size_t)(r0 + a_row) * 1024 + a_c0;
    const float* Bp = W + (size_t)b_row * 1024 + n0 + b_c0;

    const uint32_t sbase = smem_u32(sm);
    const uint32_t as_dst = sbase + (a_row * AS_LD + a_c0) * 4;
    const uint32_t bs_dst = sbase + (A_ST_F + b_row * BS_LD + b_c0) * 4;

    CFrag acc[2][4];
#pragma unroll
    for (int i = 0; i < 2; ++i)
#pragma unroll
        for (int j = 0; j < 4; ++j) wmma::fill_fragment(acc[i][j], 0.f);

#pragma unroll
    for (int s = 0; s < GS - 1; ++s) {
        const uint32_t so = s * STAGE_F * 4;
        const float* ap = Ap + s * 16;
        const float* bp = Bp + (size_t)s * 16 * 1024;
        cpasync16(as_dst + so,      ap);
        cpasync16(as_dst + so + 16, ap + 4);
        cpasync16(bs_dst + so,      bp);
        cpasync16(bs_dst + so + 16, bp + 4);
        CP_COMMIT();
    }

    for (int kt = 0; kt < 64; ++kt) {
        CP_WAIT(1);
        __syncthreads();
        if (kt + 2 < 64) {
            const int s = (kt + 2) % GS;
            const uint32_t so = s * STAGE_F * 4;
            const float* ap = Ap + (kt + 2) * 16;
            const float* bp = Bp + (size_t)(kt + 2) * 16 * 1024;
            cpasync16(as_dst + so,      ap);
            cpasync16(as_dst + so + 16, ap + 4);
            cpasync16(bs_dst + so,      bp);
            cpasync16(bs_dst + so + 16, bp + 4);
        }
        CP_COMMIT();

        const float* As = sm + (kt % GS) * STAGE_F;
        const float* Bs = As + A_ST_F;
#pragma unroll
        for (int ks = 0; ks < 16; ks += 8) {
            AFrag af[2];
#pragma unroll
            for (int i = 0; i < 2; ++i)
                wmma::load_matrix_sync(af[i], &As[(wm * 32 + i * 16) * AS_LD + ks], AS_LD);
            BFragRow bf[4];
#pragma unroll
            for (int j = 0; j < 4; ++j)
                wmma::load_matrix_sync(bf[j], &Bs[ks * BS_LD + wn * 64 + j * 16], BS_LD);
#pragma unroll
            for (int i = 0; i < 2; ++i)
#pragma unroll
                for (int j = 0; j < 4; ++j)
                    wmma::mma_sync(acc[i][j], af[i], bf[j], acc[i][j]);
        }
    }

    CP_WAIT(0);
    __syncthreads();

    float* Cs = sm;
#pragma unroll
    for (int i = 0; i < 2; ++i)
#pragma unroll
        for (int j = 0; j < 4; ++j)
            wmma::store_matrix_sync(&Cs[(wm * 32 + i * 16) * CS_LD + wn * 64 + j * 16],
                                    acc[i][j], CS_LD, wmma::mem_row_major);
    __syncthreads();

    const int er  = tid >> 1;
    const int ec0 = (tid & 1) * 64;
#pragma unroll
    for (int qq = 0; qq < 16; ++qq) {
        const int c = ec0 + qq * 4;
        float4 bb = *(const float4*)(bias + n0 + c);
        const float* cp = &Cs[er * CS_LD + c];
        float4 val;
        val.x = cp[0] + bb.x; val.y = cp[1] + bb.y;
        val.z = cp[2] + bb.z; val.w = cp[3] + bb.w;
        if (relu_residual) {
            float4 rr = *(const float4*)(R + (size_t)(r0 + er) * 1024 + n0 + c);
            val.x = rr.x + fmaxf(val.x, 0.f);
            val.y = rr.y + fmaxf(val.y, 0.f);
            val.z = rr.z + fmaxf(val.z, 0.f);
            val.w = rr.w + fmaxf(val.w, 0.f);
        }
        if (round_out) {
            val.x = to_tf32(val.x); val.y = to_tf32(val.y);
            val.z = to_tf32(val.z); val.w = to_tf32(val.w);
        }
        *(float4*)(C + (size_t)(r0 + er) * 1024 + n0 + c) = val;
    }
}

// elementwise tf32 RNA rounding (float4)
__global__ __launch_bounds__(256)
void round_tf32_kernel(const float* __restrict__ in, float* __restrict__ out)
{
    const size_t i = (size_t)blockIdx.x * blockDim.x + threadIdx.x;
    float4 v = ((const float4*)in)[i];
    v.x = to_tf32(v.x); v.y = to_tf32(v.y);
    v.z = to_tf32(v.z); v.w = to_tf32(v.w);
    ((float4*)out)[i] = v;
}

// ===========================================================================
// Fragment-layout packing kernels.
// mma.m16n8k8.tf32 layouts (lane t, regs i):
//   A: a0:(r=t/4,     c=t%4)   a1:(r=t/4+8, c=t%4)
//      a2:(r=t/4,     c=t%4+4) a3:(r=t/4+8, c=t%4+4)
//   B (col-major 8x8): b0:(k=t%4, n=t/4)  b1:(k=t%4+4, n=t/4)
//   C: c0:(r=t/4, c=2(t%4)) c1:(+0,+1) c2:(r+8, c) c3:(r+8, c+1)
// ===========================================================================

// Q -> g_qa: [b][tile16][h][wr4][kc16][lane32][4regs], rounded
__global__ __launch_bounds__(256)
void pack_q_kernel(const float* __restrict__ q, float* __restrict__ out)
{
    const int f = blockIdx.x * 256 + threadIdx.x;     // float4 index, 2M total
    const int lane = f & 31;
    const int kc   = (f >> 5) & 15;
    const int wr   = (f >> 9) & 3;
    const int h    = (f >> 11) & 7;
    const int tile = (f >> 14) & 15;
    const int b    = f >> 18;
    const int row  = tile * 64 + wr * 16 + (lane >> 2);    // within batch b
    const int col  = h * 128 + kc * 8 + (lane & 3);
    const float* qb = q + (size_t)b * CNQ * CD;
    float4 o;
    o.x = to_tf32(qb[(size_t)row * CD + col]);
    o.y = to_tf32(qb[(size_t)(row + 8) * CD + col]);
    o.z = to_tf32(qb[(size_t)row * CD + col + 4]);
    o.w = to_tf32(qb[(size_t)(row + 8) * CD + col + 4]);
    ((float4*)out)[f] = o;
}

// K -> g_k2: [b][h][ktile32][nc8][kcp8][lane32][4regs]  (k already rounded)
// regs: (b0,b1 of kc=2kcp), (b0,b1 of kc=2kcp+1)
__global__ __launch_bounds__(256)
void pack_k_kernel(const float* __restrict__ k, float* __restrict__ out)
{
    const int f = blockIdx.x * 256 + threadIdx.x;     // 4M total
    const int lane = f & 31;
    const int kcp  = (f >> 5) & 7;
    const int nc   = (f >> 8) & 7;
    const int kt   = (f >> 11) & 31;
    const int h    = (f >> 16) & 7;
    const int b    = f >> 19;
    const int token = kt * 64 + nc * 8 + (lane >> 2);
    const int d0    = h * 128 + kcp * 16 + (lane & 3);
    const float* kb = k + (size_t)b * CNK * CD + (size_t)token * CD;
    float4 o;
    o.x = kb[d0];
    o.y = kb[d0 + 4];
    o.z = kb[d0 + 8];
    o.w = kb[d0 + 12];
    ((float4*)out)[f] = o;
}

// V -> g_v2: [b][h][ktile32][half2][kcp2][nc16][lane32][4regs]
// regs: (b0,b1 of j-chunk 2kcp), (b0,b1 of j-chunk 2kcp+1)
__global__ __launch_bounds__(256)
void pack_v_kernel(const float* __restrict__ v, float* __restrict__ out)
{
    const int f = blockIdx.x * 256 + threadIdx.x;     // 4M total
    const int lane = f & 31;
    const int nc   = (f >> 5) & 15;
    const int kcp  = (f >> 9) & 1;
    const int half = (f >> 10) & 1;
    const int kt   = (f >> 11) & 31;
    const int h    = (f >> 16) & 7;
    const int b    = f >> 19;
    const int d    = h * 128 + nc * 8 + (lane >> 2);
    const int j0   = kt * 64 + half * 32 + kcp * 16 + (lane & 3);
    const float* vb = v + (size_t)b * CNK * CD;
    float4 o;
    o.x = vb[(size_t)j0 * CD + d];
    o.y = vb[(size_t)(j0 + 4) * CD + d];
    o.z = vb[(size_t)(j0 + 8) * CD + d];
    o.w = vb[(size_t)(j0 + 12) * CD + d];
    ((float4*)out)[f] = o;
}

// ===========================================================================
// Attention v4: manual mma.m16n8k8.tf32, fragment-permuted operands,
// all LDS.128 fragment loads, exp in registers, no-max softmax.
// CTA: 64 q rows x (b,h); 8 warps (wr=w&3 row group, wc=w>>2 col half); occ 2.
// smem floats: QS 8192 | KS 8192 | VS 4096 | PS 4096 | lrow2 128
// ===========================================================================
static constexpr int AQS_F = 0;
static constexpr int AKS_F = 8192;
static constexpr int AVS_F = 16384;
static constexpr int APS_F = 20480;
static constexpr int ALR_F = 24576;
static constexpr int ATT4_SMEM_BYTES = (ALR_F + 128) * 4;   // 98816 B

__device__ __forceinline__ void cp_flat(uint32_t dst, const float* src,
                                        int tid, int n16)
{
    for (int i = tid; i < n16; i += 256)
        cpasync16(dst + i * 16, src + i * 4);
}

__global__ __launch_bounds__(256, 2)
void attn4_kernel(const float* __restrict__ qa, const float* __restrict__ qe,
                  const float* __restrict__ k2, const float* __restrict__ v2,
                  float* __restrict__ x)
{
    extern __shared__ float sm[];
    const float4* QS4 = (const float4*)(sm + AQS_F);
    const float4* KS4 = (const float4*)(sm + AKS_F);
    const float4* VS4 = (const float4*)(sm + AVS_F);
    float*        PS  = sm + APS_F;
    const float4* PS4 = (const float4*)PS;
    float*        lrow2 = sm + ALR_F;

    const int b    = blockIdx.z;
    const int h    = blockIdx.y;
    const int tile = blockIdx.x;

    const float* qa_tile = qa + (((size_t)(b * 16 + tile) * 8 + h) << 13);
    const float* k_base  = k2 + (((size_t)(b * 8 + h)) << 18);   // 32 tiles * 8192
    const float* v_base  = v2 + (((size_t)(b * 8 + h)) << 18);
    const float* qeb = qe + ((size_t)(b * CNQ + tile * 64)) * CD + h * CDH;
    float*       xb  = x  + ((size_t)(b * CNQ + tile * 64)) * CD + h * CDH;

    const int tid  = threadIdx.x;
    const int lane = tid & 31;
    const int w    = tid >> 5;
    const int wr   = w & 3;     // 16-row group
    const int wc   = w >> 2;    // column half

    const uint32_t qs_u = smem_u32(sm + AQS_F);
    const uint32_t ks_u = smem_u32(sm + AKS_F);
    const uint32_t vs_u = smem_u32(sm + AVS_F);

    // prologue: Q | K0 | V0-half0
    cp_flat(qs_u, qa_tile, tid, 2048); CP_COMMIT();
    cp_flat(ks_u, k_base, tid, 2048);  CP_COMMIT();
    cp_flat(vs_u, v_base, tid, 1024);  CP_COMMIT();

    if (tid < 128) lrow2[tid] = 0.f;

    float oacc[8][4];
#pragma unroll
    for (int n = 0; n < 8; ++n)
#pragma unroll
        for (int i = 0; i < 4; ++i) oacc[n][i] = 0.f;

    const float scale = 0.03125f;   // 1/sqrt(1024)

    CP_WAIT(1);          // Q, K0 resident (Vh0 may fly)
    __syncthreads();

    for (int kt = 0; kt < 32; ++kt) {
        // ---- S = Q @ K^T : warp -> rows [wr*16,+16), cols [wc*32,+32) ----
        float sacc[4][4];
#pragma unroll
        for (int n = 0; n < 4; ++n)
#pragma unroll
            for (int i = 0; i < 4; ++i) sacc[n][i] = 0.f;

#pragma unroll
        for (int kcp = 0; kcp < 8; ++kcp) {
            float4 a0 = QS4[(wr * 16 + 2 * kcp) * 32 + lane];
            float4 a1 = QS4[(wr * 16 + 2 * kcp + 1) * 32 + lane];
#pragma unroll
            for (int n = 0; n < 4; ++n) {
                float4 bb = KS4[((wc * 4 + n) * 8 + kcp) * 32 + lane];
                mma1688(sacc[n], a0, bb.x, bb.y);
                mma1688(sacc[n], a1, bb.z, bb.w);
            }
        }
        __syncthreads();                       // [1] Ks consumed

        // prefetch K_{kt+1}
        if (kt + 1 < 32) cp_flat(ks_u, k_base + ((size_t)(kt + 1) << 13), tid, 2048);
        CP_COMMIT();                           // pending: [Vh0, K']

        // ---- exp in regs, store P into PV-A layout, accumulate lrow ----
        {
            float sum0 = 0.f, sum1 = 0.f;
#pragma unroll
            for (int n = 0; n < 4; ++n) {
                const int jcg = wc * 4 + n;
#pragma unroll
                for (int i = 0; i < 4; ++i) {
                    float p = __expf(sacc[n][i] * scale);
                    if (i < 2) sum0 += p; else sum1 += p;
                    const int r16 = (lane >> 2) + ((i >> 1) << 3);
                    const int jl  = ((lane & 3) << 1) + (i & 1);
                    const int l2  = ((r16 & 7) << 2) + (jl & 3);
                    const int i2  = ((jl >> 2) << 1) + (r16 >> 3);
                    PS[(wr * 8 + jcg) * 128 + l2 * 4 + i2] = to_tf32(p);
                }
            }
            sum0 += __shfl_xor_sync(0xffffffffu, sum0, 1);
            sum0 += __shfl_xor_sync(0xffffffffu, sum0, 2);
            sum1 += __shfl_xor_sync(0xffffffffu, sum1, 1);
            sum1 += __shfl_xor_sync(0xffffffffu, sum1, 2);
            if ((lane & 3) == 0) {
                const int r = wr * 16 + (lane >> 2);
                lrow2[wc * 64 + r]     += sum0;
                lrow2[wc * 64 + r + 8] += sum1;
            }
        }

        CP_WAIT(1);                            // Vh0 resident (K' flying)
        __syncthreads();                       // [2] PS + Vs(h0) visible

        // ---- PV half 0: O += P[:,0:32] @ V[0:32,:] ----
#pragma unroll
        for (int kcp2 = 0; kcp2 < 2; ++kcp2) {
            float4 p0 = PS4[(wr * 8 + 2 * kcp2) * 32 + lane];
            float4 p1 = PS4[(wr * 8 + 2 * kcp2 + 1) * 32 + lane];
#pragma unroll
            for (int n = 0; n < 8; ++n) {
                float4 bb = VS4[(kcp2 * 16 + wc * 8 + n) * 32 + lane];
                mma1688(oacc[n], p0, bb.x, bb.y);
                mma1688(oacc[n], p1, bb.z, bb.w);
            }
        }
        __syncthreads();                       // [3] Vs consumed

        cp_flat(vs_u, v_base + (((size_t)kt * 2 + 1) << 12), tid, 1024);
        CP_COMMIT();                           // pending: [K', Vh1]
        CP_WAIT(0);                            // both resident
        __syncthreads();                       // [4]

        // ---- PV half 1: O += P[:,32:64] @ V[32:64,:] ----
#pragma unroll
        for (int kcp2 = 0; kcp2 < 2; ++kcp2) {
            float4 p0 = PS4[(wr * 8 + 4 + 2 * kcp2) * 32 + lane];
            float4 p1 = PS4[(wr * 8 + 4 + 2 * kcp2 + 1) * 32 + lane];
#pragma unroll
            for (int n = 0; n < 8; ++n) {
                float4 bb = VS4[(kcp2 * 16 + wc * 8 + n) * 32 + lane];
                mma1688(oacc[n], p0, bb.x, bb.y);
                mma1688(oacc[n], p1, bb.z, bb.w);
            }
        }
        __syncthreads();                       // [5] Vs consumed

        if (kt + 1 < 32) cp_flat(vs_u, v_base + (((size_t)(kt + 1) * 2) << 12), tid, 1024);
        CP_COMMIT();                           // pending: [Vh0']
    }

    __syncthreads();   // lrow2 final

    // ---- epilogue: x = q_exact + O / l  (direct to gmem) ----
    {
        const int r0 = wr * 16 + (lane >> 2);
        const float inv0 = 1.f / (lrow2[r0] + lrow2[64 + r0]);
        const float inv8 = 1.f / (lrow2[r0 + 8] + lrow2[64 + r0 + 8]);
#pragma unroll
        for (int n = 0; n < 8; ++n) {
            const int d = wc * 64 + n * 8 + ((lane & 3) << 1);
            const float* q0 = qeb + (size_t)r0 * CD + d;
            const float* q8 = qeb + (size_t)(r0 + 8) * CD + d;
            float2 o0, o8;
            o0.x = fmaf(oacc[n][0], inv0, q0[0]);
            o0.y = fmaf(oacc[n][1], inv0, q0[1]);
            o8.x = fmaf(oacc[n][2], inv8, q8[0]);
            o8.y = fmaf(oacc[n][3], inv8, q8[1]);
            *(float2*)(xb + (size_t)r0 * CD + d)       = o0;
            *(float2*)(xb + (size_t)(r0 + 8) * CD + d) = o8;
        }
    }
}

// ===========================================================================
// Row LayerNorm over 1024 columns.
// ===========================================================================
__global__ __launch_bounds__(256)
void ln_kernel(const float* __restrict__ in, float* __restrict__ out,
               const float* __restrict__ g, const float* __restrict__ bta)
{
    __shared__ float red_s[8], red_s2[8];
    __shared__ float mu_s, rs_s;
    const int row = blockIdx.x;
    const int tid = threadIdx.x;
    const float* rp = in + (size_t)row * 1024;

    float4 xv = *(const float4*)(rp + tid * 4);
    float s  = xv.x + xv.y + xv.z + xv.w;
    float s2 = xv.x * xv.x + xv.y * xv.y + xv.z * xv.z + xv.w * xv.w;
#pragma unroll
    for (int off = 16; off >= 1; off >>= 1) {
        s  += __shfl_xor_sync(0xffffffffu, s,  off);
        s2 += __shfl_xor_sync(0xffffffffu, s2, off);
    }
    if ((tid & 31) == 0) { red_s[tid >> 5] = s; red_s2[tid >> 5] = s2; }
    __syncthreads();
    if (tid == 0) {
        float a = 0.f, a2 = 0.f;
#pragma unroll
        for (int wq = 0; wq < 8; ++wq) { a += red_s[wq]; a2 += red_s2[wq]; }
        const float mu  = a * (1.f / 1024.f);
        const float var = a2 * (1.f / 1024.f) - mu * mu;
        mu_s = mu;
        rs_s = rsqrtf(var + 1e-5f);
    }
    __syncthreads();
    const float mu = mu_s, rs = rs_s;
    float4 gv = *(const float4*)(g + tid * 4);
    float4 bv = *(const float4*)(bta + tid * 4);
    float4 ov;
    ov.x = (xv.x - mu) * rs * gv.x + bv.x;
    ov.y = (xv.y - mu) * rs * gv.y + bv.y;
    ov.z = (xv.z - mu) * rs * gv.z + bv.z;
    ov.w = (xv.w - mu) * rs * gv.w + bv.w;
    *(float4*)(out + (size_t)row * 1024 + tid * 4) = ov;
}

// ===========================================================================
extern "C" void kernel_launch(void* const* d_in, const int* in_sizes, int n_in,
                              void* d_out, int out_size)
{
    const float* Q  = (const float*)d_in[0];
    const float* K  = (const float*)d_in[1];
    const float* Wq = (const float*)d_in[2];
    const float* bq = (const float*)d_in[3];
    const float* Wk = (const float*)d_in[4];
    const float* bk = (const float*)d_in[5];
    const float* Wv = (const float*)d_in[6];
    const float* bv = (const float*)d_in[7];
    const float* Wo = (const float*)d_in[8];
    const float* bo = (const float*)d_in[9];
    const float* g0 = (const float*)d_in[10];
    const float* b0 = (const float*)d_in[11];
    const float* g1 = (const float*)d_in[12];
    const float* b1 = (const float*)d_in[13];
    float* out = (float*)d_out;

    float *qp, *qap, *kp, *vp, *k2p, *v2p, *xp, *yp, *wrp, *qrp, *krp, *xrp;
    cudaGetSymbolAddress((void**)&qp,  g_q);
    cudaGetSymbolAddress((void**)&qap, g_qa);
    cudaGetSymbolAddress((void**)&kp,  g_k);
    cudaGetSymbolAddress((void**)&vp,  g_v);
    cudaGetSymbolAddress((void**)&k2p, g_k2);
    cudaGetSymbolAddress((void**)&v2p, g_v2);
    cudaGetSymbolAddress((void**)&xp,  g_x);
    cudaGetSymbolAddress((void**)&yp,  g_y);
    cudaGetSymbolAddress((void**)&wrp, g_wr);
    cudaGetSymbolAddress((void**)&qrp, g_qr);
    cudaGetSymbolAddress((void**)&krp, g_kr);
    cudaGetSymbolAddress((void**)&xrp, g_xr);

    cudaFuncSetAttribute(gemm_pipe_kernel,
                         cudaFuncAttributeMaxDynamicSharedMemorySize,
                         GEMM_SMEM_BYTES);
    cudaFuncSetAttribute(attn4_kernel,
                         cudaFuncAttributeMaxDynamicSharedMemorySize,
                         ATT4_SMEM_BYTES);

    // prep: tf32-round activations + weights
    round_tf32_kernel<<<CB * CNQ * CD / 1024, 256>>>(Q, qrp);
    round_tf32_kernel<<<CB * CNK * CD / 1024, 256>>>(K, krp);
    round_tf32_kernel<<<CD * CD / 1024, 256>>>(Wq, wrp + 0 * CD * CD);
    round_tf32_kernel<<<CD * CD / 1024, 256>>>(Wk, wrp + 1 * CD * CD);
    round_tf32_kernel<<<CD * CD / 1024, 256>>>(Wv, wrp + 2 * CD * CD);
    round_tf32_kernel<<<CD * CD / 1024, 256>>>(Wo, wrp + 3 * CD * CD);

    // projections: q exact fp32; k/v rounded (row-major)
    gemm_pipe_kernel<<<dim3(8,  64), 256, GEMM_SMEM_BYTES>>>(qrp, wrp + 0 * CD * CD, bq, nullptr, qp, 0, 0);
    gemm_pipe_kernel<<<dim3(8, 128), 256, GEMM_SMEM_BYTES>>>(krp, wrp + 1 * CD * CD, bk, nullptr, kp, 0, 1);
    gemm_pipe_kernel<<<dim3(8, 128), 256, GEMM_SMEM_BYTES>>>(krp, wrp + 2 * CD * CD, bv, nullptr, vp, 0, 1);

    // fragment-layout packing
    pack_q_kernel<<<CB * CNQ * CD / 4 / 256, 256>>>(qp, qap);
    pack_k_kernel<<<CB * CNK * CD / 4 / 256, 256>>>(kp, k2p);
    pack_v_kernel<<<CB * CNK * CD / 4 / 256, 256>>>(vp, v2p);

    // attention + residual (manual mma, occ 2)
    attn4_kernel<<<dim3(16, CH, CB), 256, ATT4_SMEM_BYTES>>>(qap, qp, k2p, v2p, xp);
    // LN0 (in place)
    ln_kernel<<<CB * CNQ, 256>>>(xp, xp, g0, b0);
    // y = x + relu(x @ Wo + bo)
    round_tf32_kernel<<<CB * CNQ * CD / 1024, 256>>>(xp, xrp);
    gemm_pipe_kernel<<<dim3(8, 64), 256, GEMM_SMEM_BYTES>>>(xrp, wrp + 3 * CD * CD, bo, xp, yp, 1, 0);
    // LN1 -> out
    ln_kernel<<<CB * CNQ, 256>>>(yp, out, g1, b1);
}

// round 13
// speedup vs baseline: 5.6279x; 2.7008x over previous
#include <cuda_runtime.h>
#include <cuda_fp16.h>
#include <math.h>
#include <stddef.h>
#include <stdint.h>

static constexpr int CB  = 8;     // batch
static constexpr int CNQ = 1024;  // query tokens
static constexpr int CNK = 2048;  // key tokens
static constexpr int CD  = 1024;  // model dim
static constexpr int CH  = 8;     // heads
static constexpr int CDH = 128;   // head dim

// ---------------- scratch (no allocations allowed -> device globals) -------
__device__ float g_q[CB * CNQ * CD];    // q projection (fp32 exact, residual)
__device__ float g_k[CB * CNK * CD];    // k projection (fp32 row-major)
__device__ float g_v[CB * CNK * CD];    // v projection (fp32 row-major)
__device__ float g_x[CB * CNQ * CD];    // attn out / LN0 out
__device__ float g_y[CB * CNQ * CD];    // pre-LN1
__device__ uint4 g_apk[2097152];        // GEMM A packed (fp16 frags), 32 MB max
__device__ uint4 g_wpk[4][131072];      // weights packed (fp16 B-frags), 2 MB each
__device__ uint4 g_qpk[1048576];        // attn Q packed (A-frags), 16 MB
__device__ uint4 g_kpk[2097152];        // attn K packed (S B-frags), 32 MB
__device__ uint4 g_vpk[2097152];        // attn V packed (PV B-frags), 32 MB

__device__ __forceinline__ uint32_t f2h2(float a, float b) {
    __half2 h = __floats2half2_rn(a, b);
    return *reinterpret_cast<uint32_t*>(&h);
}

__device__ __forceinline__ uint32_t smem_u32(const void* p) {
    uint32_t a;
    asm("{ .reg .u64 t; cvta.to.shared.u64 t, %1; cvt.u32.u64 %0, t; }"
        : "=r"(a) : "l"(p));
    return a;
}

__device__ __forceinline__ void cpasync16(uint32_t dst, const void* src) {
    asm volatile("cp.async.cg.shared.global [%0], [%1], 16;"
                 :: "r"(dst), "l"(src));
}
#define CP_COMMIT() asm volatile("cp.async.commit_group;" ::: "memory")
#define CP_WAIT(n)  asm volatile("cp.async.wait_group %0;" :: "n"(n) : "memory")

// fp16 mma: D(16x8,f32) += A(16x16,f16 row) * B(16x8,f16 col)
__device__ __forceinline__ void mma16816(float* c, uint4 a, uint32_t b0, uint32_t b1) {
    asm volatile(
        "mma.sync.aligned.m16n8k16.row.col.f32.f16.f16.f32 "
        "{%0,%1,%2,%3}, {%4,%5,%6,%7}, {%8,%9}, {%0,%1,%2,%3};"
        : "+f"(c[0]), "+f"(c[1]), "+f"(c[2]), "+f"(c[3])
        : "r"(a.x), "r"(a.y), "r"(a.z), "r"(a.w), "r"(b0), "r"(b1));
}

// ===========================================================================
// Packing kernels. m16n8k16 fragment layouts (lane = 4g + t):
//   A(16x16): R0={A[g][2t],A[g][2t+1]} R1={A[g+8][2t],+1} R2={A[g][2t+8],+9} R3={A[g+8][2t+8],+9}
//   B(16x8 col): R0={B[2t][g],B[2t+1][g]} R1={B[2t+8][g],B[2t+9][g]}
//   C(16x8 f32): c0=(g,2t) c1=(g,2t+1) c2=(g+8,2t) c3=(g+8,2t+1)
// ===========================================================================

// activations -> A-frag layout [rowtile][kc64][lane]  (fp32 in, fp16 out)
__global__ __launch_bounds__(256)
void pack_a_kernel(const float* __restrict__ in, uint4* __restrict__ out)
{
    const int f = blockIdx.x * 256 + threadIdx.x;
    const int lane = f & 31, kc = (f >> 5) & 63, rt = f >> 11;
    const int g = lane >> 2, t = lane & 3;
    const float* r0 = in + (size_t)(rt * 16 + g) * CD + kc * 16 + 2 * t;
    const float* r8 = r0 + 8 * CD;
    uint4 o;
    o.x = f2h2(r0[0], r0[1]);
    o.y = f2h2(r8[0], r8[1]);
    o.z = f2h2(r0[8], r0[9]);
    o.w = f2h2(r8[8], r8[9]);
    out[f] = o;
}

// W[1024,1024] -> B-frag layout [ctile8][kc64][wn2][pair4][lane]
__global__ __launch_bounds__(256)
void pack_w_kernel(const float* __restrict__ w, uint4* __restrict__ out)
{
    const int f = blockIdx.x * 256 + threadIdx.x;
    const int lane = f & 31, pair = (f >> 5) & 3, wn = (f >> 7) & 1;
    const int kc = (f >> 8) & 63, ct = f >> 14;
    const int g = lane >> 2, t = lane & 3;
    const int k0 = kc * 16 + 2 * t;
    const int c0 = ct * 128 + (wn * 8 + pair * 2) * 8 + g;
    const int c1 = c0 + 8;
    uint4 o;
    o.x = f2h2(w[(size_t)k0 * CD + c0],       w[(size_t)(k0 + 1) * CD + c0]);
    o.y = f2h2(w[(size_t)(k0 + 8) * CD + c0], w[(size_t)(k0 + 9) * CD + c0]);
    o.z = f2h2(w[(size_t)k0 * CD + c1],       w[(size_t)(k0 + 1) * CD + c1]);
    o.w = f2h2(w[(size_t)(k0 + 8) * CD + c1], w[(size_t)(k0 + 9) * CD + c1]);
    out[f] = o;
}

// q proj -> attn A-frag layout [b][tile16][h][wr4][kc8][lane]
__global__ __launch_bounds__(256)
void pack_q_kernel(const float* __restrict__ q, uint4* __restrict__ out)
{
    const int f = blockIdx.x * 256 + threadIdx.x;
    const int lane = f & 31, kc = (f >> 5) & 7, wr = (f >> 8) & 3;
    const int h = (f >> 10) & 7, tile = (f >> 13) & 15, b = f >> 17;
    const int g = lane >> 2, t = lane & 3;
    const int row = tile * 64 + wr * 16 + g;
    const int c0  = h * 128 + kc * 16 + 2 * t;
    const float* r0 = q + ((size_t)b * CNQ + row) * CD + c0;
    const float* r8 = r0 + 8 * CD;
    uint4 o;
    o.x = f2h2(r0[0], r0[1]);
    o.y = f2h2(r8[0], r8[1]);
    o.z = f2h2(r0[8], r0[9]);
    o.w = f2h2(r8[8], r8[9]);
    out[f] = o;
}

// k proj -> S B-frag layout [b][h][kt32][kc8][wc2][pair2][lane]
__global__ __launch_bounds__(256)
void pack_k_kernel(const float* __restrict__ k, uint4* __restrict__ out)
{
    const int f = blockIdx.x * 256 + threadIdx.x;
    const int lane = f & 31, pair = (f >> 5) & 1, wc = (f >> 6) & 1;
    const int kc = (f >> 7) & 7, kt = (f >> 10) & 31, h = (f >> 15) & 7, b = f >> 18;
    const int g = lane >> 2, t = lane & 3;
    const int tok0 = kt * 64 + (wc * 4 + pair * 2) * 8 + g;
    const int d0   = h * 128 + kc * 16 + 2 * t;
    const float* p0 = k + ((size_t)b * CNK + tok0) * CD + d0;
    const float* p1 = p0 + 8 * CD;   // tok0 + 8
    uint4 o;
    o.x = f2h2(p0[0], p0[1]);
    o.y = f2h2(p0[8], p0[9]);
    o.z = f2h2(p1[0], p1[1]);
    o.w = f2h2(p1[8], p1[9]);
    out[f] = o;
}

// v proj -> PV B-frag layout [b][h][kt32][jc4][wcd2][pair4][lane]
__global__ __launch_bounds__(256)
void pack_v_kernel(const float* __restrict__ v, uint4* __restrict__ out)
{
    const int f = blockIdx.x * 256 + threadIdx.x;
    const int lane = f & 31, pair = (f >> 5) & 3, wcd = (f >> 7) & 1;
    const int jc = (f >> 8) & 3, kt = (f >> 10) & 31, h = (f >> 15) & 7, b = f >> 18;
    const int g = lane >> 2, t = lane & 3;
    const int j0 = kt * 64 + jc * 16 + 2 * t;
    const int d0 = h * 128 + (wcd * 8 + pair * 2) * 8 + g;
    const int d1 = d0 + 8;
    const float* vb = v + (size_t)b * CNK * CD;
    uint4 o;
    o.x = f2h2(vb[(size_t)j0 * CD + d0],       vb[(size_t)(j0 + 1) * CD + d0]);
    o.y = f2h2(vb[(size_t)(j0 + 8) * CD + d0], vb[(size_t)(j0 + 9) * CD + d0]);
    o.z = f2h2(vb[(size_t)j0 * CD + d1],       vb[(size_t)(j0 + 1) * CD + d1]);
    o.w = f2h2(vb[(size_t)(j0 + 8) * CD + d1], vb[(size_t)(j0 + 9) * CD + d1]);
    out[f] = o;
}

// ===========================================================================
// fp16 GEMM: C[M,1024] = A @ W + bias   (+ optional R + relu residual)
// Packed operands; 128x128 tile, k16 chunks, 3-stage cp.async, 8 warps.
// ===========================================================================
static constexpr int G16_STAGES = 3;
static constexpr int G16_SMEM_BYTES = G16_STAGES * 512 * 16;   // 24 KB

__global__ __launch_bounds__(256, 2)
void gemm_f16_kernel(const uint4* __restrict__ Apk, const uint4* __restrict__ Wpk,
                     const float* __restrict__ bias, const float* __restrict__ R,
                     float* __restrict__ C, int relu_residual)
{
    extern __shared__ uint4 smu[];
    const int tid  = threadIdx.x;
    const int lane = tid & 31;
    const int w    = tid >> 5;
    const int wm   = w & 3;      // 32-row group
    const int wn   = w >> 2;     // 64-col group
    const int rt0  = blockIdx.y * 8;     // rowtile base (16-row tiles)
    const int ct   = blockIdx.x;         // 128-col tile

    const uint32_t sbase = smem_u32(smu);
    const int art = tid >> 5;            // rowtile 0..7 for this thread's A cp

    float acc[2][8][4];
#pragma unroll
    for (int i = 0; i < 2; ++i)
#pragma unroll
        for (int n = 0; n < 8; ++n)
#pragma unroll
            for (int c = 0; c < 4; ++c) acc[i][n][c] = 0.f;

#pragma unroll
    for (int s = 0; s < G16_STAGES - 1; ++s) {
        cpasync16(sbase + (s * 512 + tid) * 16,
                  Apk + ((size_t)(rt0 + art) * 64 + s) * 32 + lane);
        cpasync16(sbase + (s * 512 + 256 + tid) * 16,
                  Wpk + ((size_t)ct * 64 + s) * 256 + tid);
        CP_COMMIT();
    }

    for (int kc = 0; kc < 64; ++kc) {
        CP_WAIT(1);
        __syncthreads();
        if (kc + 2 < 64) {
            const int s = (kc + 2) % G16_STAGES;
            cpasync16(sbase + (s * 512 + tid) * 16,
                      Apk + ((size_t)(rt0 + art) * 64 + kc + 2) * 32 + lane);
            cpasync16(sbase + (s * 512 + 256 + tid) * 16,
                      Wpk + ((size_t)ct * 64 + kc + 2) * 256 + tid);
        }
        CP_COMMIT();

        const uint4* As = smu + (kc % G16_STAGES) * 512;
        const uint4* Bs = As + 256;
        uint4 af[2];
#pragma unroll
        for (int i = 0; i < 2; ++i) af[i] = As[(2 * wm + i) * 32 + lane];
#pragma unroll
        for (int p = 0; p < 4; ++p) {
            uint4 bf = Bs[(wn * 4 + p) * 32 + lane];
#pragma unroll
            for (int i = 0; i < 2; ++i) {
                mma16816(acc[i][2 * p],     af[i], bf.x, bf.y);
                mma16816(acc[i][2 * p + 1], af[i], bf.z, bf.w);
            }
        }
    }
    CP_WAIT(0);

    // epilogue: registers -> gmem
    const int g = lane >> 2, t = lane & 3;
#pragma unroll
    for (int i = 0; i < 2; ++i) {
        const int r = blockIdx.y * 128 + wm * 32 + i * 16 + g;
#pragma unroll
        for (int n = 0; n < 8; ++n) {
            const int col = ct * 128 + wn * 64 + n * 8 + 2 * t;
            float2 bb = *(const float2*)(bias + col);
            float2 v0, v8;
            v0.x = acc[i][n][0] + bb.x; v0.y = acc[i][n][1] + bb.y;
            v8.x = acc[i][n][2] + bb.x; v8.y = acc[i][n][3] + bb.y;
            if (relu_residual) {
                float2 r0 = *(const float2*)(R + (size_t)r * CD + col);
                float2 r8 = *(const float2*)(R + (size_t)(r + 8) * CD + col);
                v0.x = r0.x + fmaxf(v0.x, 0.f); v0.y = r0.y + fmaxf(v0.y, 0.f);
                v8.x = r8.x + fmaxf(v8.x, 0.f); v8.y = r8.y + fmaxf(v8.y, 0.f);
            }
            *(float2*)(C + (size_t)r * CD + col)       = v0;
            *(float2*)(C + (size_t)(r + 8) * CD + col) = v8;
        }
    }
}

// ===========================================================================
// Attention v5 (fp16 manual mma): 64 q rows/CTA, K/V whole-tile double
// buffer, P in registers, 1 barrier/iter, no-max softmax.
// smem u4: Qs[0,1024) | K[1024,3072) | V[3072,5120) | lrow2 (128 f)
// ===========================================================================
static constexpr int ATT5_SMEM_BYTES = 5120 * 16 + 128 * 4;   // 82432

__global__ __launch_bounds__(256, 2)
void attn5_kernel(const uint4* __restrict__ qpk, const float* __restrict__ qe,
                  const uint4* __restrict__ kpk, const uint4* __restrict__ vpk,
                  float* __restrict__ x)
{
    extern __shared__ uint4 smu[];
    const uint4* Qs = smu;
    float* lrow2 = (float*)(smu + 5120);
    float* stg   = (float*)(smu + 3072);   // epilogue f32 stage (V region, 8192 f)

    const int b    = blockIdx.z;
    const int h    = blockIdx.y;
    const int tile = blockIdx.x;
    const int tid  = threadIdx.x;
    const int lane = tid & 31;
    const int w    = tid >> 5;
    const int wr   = w & 3;
    const int wc   = w >> 2;
    const int g    = lane >> 2, t = lane & 3;

    const uint4* qsrc = qpk + (((size_t)(b * 16 + tile) * 8 + h) << 10);
    const uint4* kbase = kpk + (((size_t)(b * 8 + h)) << 15);   // 32 tiles * 1024
    const uint4* vbase = vpk + (((size_t)(b * 8 + h)) << 15);
    const float* qeb = qe + ((size_t)(b * CNQ + tile * 64)) * CD + h * CDH;
    float*       xb  = x  + ((size_t)(b * CNQ + tile * 64)) * CD + h * CDH;

    const uint32_t sb = smem_u32(smu);

    // prologue: Q + K0 + V0 (one group)
#pragma unroll
    for (int u = 0; u < 4; ++u)
        cpasync16(sb + (tid + u * 256) * 16, qsrc + tid + u * 256);
#pragma unroll
    for (int u = 0; u < 4; ++u)
        cpasync16(sb + (1024 + tid + u * 256) * 16, kbase + tid + u * 256);
#pragma unroll
    for (int u = 0; u < 4; ++u)
        cpasync16(sb + (3072 + tid + u * 256) * 16, vbase + tid + u * 256);
    CP_COMMIT();

    if (tid < 128) lrow2[tid] = 0.f;

    float oacc[16][4];
#pragma unroll
    for (int n = 0; n < 16; ++n)
#pragma unroll
        for (int c = 0; c < 4; ++c) oacc[n][c] = 0.f;

    const float scale = 0.03125f;   // 1/sqrt(1024)

    CP_WAIT(0);
    __syncthreads();

    for (int kt = 0; kt < 32; ++kt) {
        const int cur = kt & 1;
        // prefetch next K/V into other buffer
        if (kt + 1 < 32) {
            const int nxt = 1 - cur;
            const uint4* ks = kbase + ((size_t)(kt + 1) << 10);
            const uint4* vs = vbase + ((size_t)(kt + 1) << 10);
#pragma unroll
            for (int u = 0; u < 4; ++u)
                cpasync16(sb + (1024 + nxt * 1024 + tid + u * 256) * 16, ks + tid + u * 256);
#pragma unroll
            for (int u = 0; u < 4; ++u)
                cpasync16(sb + (3072 + nxt * 1024 + tid + u * 256) * 16, vs + tid + u * 256);
            CP_COMMIT();
        }

        const uint4* Ks = smu + 1024 + cur * 1024;
        const uint4* Vs = smu + 3072 + cur * 1024;

        // ---- S = Q @ K^T : warp -> rows wr*16, token cols wc*32 ----
        float sacc[4][4];
#pragma unroll
        for (int n = 0; n < 4; ++n)
#pragma unroll
            for (int c = 0; c < 4; ++c) sacc[n][c] = 0.f;
#pragma unroll
        for (int kc = 0; kc < 8; ++kc) {
            uint4 qf = Qs[(wr * 8 + kc) * 32 + lane];
#pragma unroll
            for (int p = 0; p < 2; ++p) {
                uint4 kf = Ks[((kc * 2 + wc) * 2 + p) * 32 + lane];
                mma16816(sacc[2 * p],     qf, kf.x, kf.y);
                mma16816(sacc[2 * p + 1], qf, kf.z, kf.w);
            }
        }

        // ---- exp in regs -> P A-frags; lrow accumulation ----
        float e[4][4];
        float sum0 = 0.f, sum1 = 0.f;
#pragma unroll
        for (int n = 0; n < 4; ++n)
#pragma unroll
            for (int c = 0; c < 4; ++c) {
                e[n][c] = __expf(sacc[n][c] * scale);
                if (c < 2) sum0 += e[n][c]; else sum1 += e[n][c];
            }
        sum0 += __shfl_xor_sync(0xffffffffu, sum0, 1);
        sum0 += __shfl_xor_sync(0xffffffffu, sum0, 2);
        sum1 += __shfl_xor_sync(0xffffffffu, sum1, 1);
        sum1 += __shfl_xor_sync(0xffffffffu, sum1, 2);
        if (t == 0) {
            const int r = wr * 16 + g;
            lrow2[wc * 64 + r]     += sum0;
            lrow2[wc * 64 + r + 8] += sum1;
        }
        uint4 pf[2];
        pf[0].x = f2h2(e[0][0], e[0][1]); pf[0].y = f2h2(e[0][2], e[0][3]);
        pf[0].z = f2h2(e[1][0], e[1][1]); pf[0].w = f2h2(e[1][2], e[1][3]);
        pf[1].x = f2h2(e[2][0], e[2][1]); pf[1].y = f2h2(e[2][2], e[2][3]);
        pf[1].z = f2h2(e[3][0], e[3][1]); pf[1].w = f2h2(e[3][2], e[3][3]);

        // ---- PV: O_partial += P[wr16, wc32] @ V[wc32, 0:128] ----
#pragma unroll
        for (int J = 0; J < 2; ++J) {
            const int jc = wc * 2 + J;
#pragma unroll
            for (int wcd = 0; wcd < 2; ++wcd)
#pragma unroll
                for (int p = 0; p < 4; ++p) {
                    uint4 vf = Vs[((jc * 2 + wcd) * 4 + p) * 32 + lane];
                    const int n = wcd * 8 + p * 2;
                    mma16816(oacc[n],     pf[J], vf.x, vf.y);
                    mma16816(oacc[n + 1], pf[J], vf.z, vf.w);
                }
        }

        CP_WAIT(0);
        __syncthreads();
    }

    // ---- epilogue: cross-warp partial sum + residual + 1/l ----
    // stage the OTHER d-half for the partner warp
    {
        const int r = wr * 16 + g;
#pragma unroll
        for (int n = (1 - wc) * 8; n < (1 - wc) * 8 + 8; ++n) {
            const int d = n * 8 + 2 * t;
            stg[r * 128 + d]           = oacc[n][0];
            stg[r * 128 + d + 1]       = oacc[n][1];
            stg[(r + 8) * 128 + d]     = oacc[n][2];
            stg[(r + 8) * 128 + d + 1] = oacc[n][3];
        }
    }
    __syncthreads();
    {
        const int r = wr * 16 + g;
        const float inv0 = 1.f / (lrow2[r] + lrow2[64 + r]);
        const float inv8 = 1.f / (lrow2[r + 8] + lrow2[64 + r + 8]);
#pragma unroll
        for (int n = wc * 8; n < wc * 8 + 8; ++n) {
            const int d = n * 8 + 2 * t;
            float2 q0 = *(const float2*)(qeb + (size_t)r * CD + d);
            float2 q8 = *(const float2*)(qeb + (size_t)(r + 8) * CD + d);
            float2 o0, o8;
            o0.x = fmaf(oacc[n][0] + stg[r * 128 + d],           inv0, q0.x);
            o0.y = fmaf(oacc[n][1] + stg[r * 128 + d + 1],       inv0, q0.y);
            o8.x = fmaf(oacc[n][2] + stg[(r + 8) * 128 + d],     inv8, q8.x);
            o8.y = fmaf(oacc[n][3] + stg[(r + 8) * 128 + d + 1], inv8, q8.y);
            *(float2*)(xb + (size_t)r * CD + d)       = o0;
            *(float2*)(xb + (size_t)(r + 8) * CD + d) = o8;
        }
    }
}

// ===========================================================================
// Row LayerNorm over 1024 columns.
// ===========================================================================
__global__ __launch_bounds__(256)
void ln_kernel(const float* __restrict__ in, float* __restrict__ out,
               const float* __restrict__ g, const float* __restrict__ bta)
{
    __shared__ float red_s[8], red_s2[8];
    __shared__ float mu_s, rs_s;
    const int row = blockIdx.x;
    const int tid = threadIdx.x;
    const float* rp = in + (size_t)row * 1024;

    float4 xv = *(const float4*)(rp + tid * 4);
    float s  = xv.x + xv.y + xv.z + xv.w;
    float s2 = xv.x * xv.x + xv.y * xv.y + xv.z * xv.z + xv.w * xv.w;
#pragma unroll
    for (int off = 16; off >= 1; off >>= 1) {
        s  += __shfl_xor_sync(0xffffffffu, s,  off);
        s2 += __shfl_xor_sync(0xffffffffu, s2, off);
    }
    if ((tid & 31) == 0) { red_s[tid >> 5] = s; red_s2[tid >> 5] = s2; }
    __syncthreads();
    if (tid == 0) {
        float a = 0.f, a2 = 0.f;
#pragma unroll
        for (int wq = 0; wq < 8; ++wq) { a += red_s[wq]; a2 += red_s2[wq]; }
        const float mu  = a * (1.f / 1024.f);
        const float var = a2 * (1.f / 1024.f) - mu * mu;
        mu_s = mu;
        rs_s = rsqrtf(var + 1e-5f);
    }
    __syncthreads();
    const float mu = mu_s, rs = rs_s;
    float4 gv = *(const float4*)(g + tid * 4);
    float4 bv = *(const float4*)(bta + tid * 4);
    float4 ov;
    ov.x = (xv.x - mu) * rs * gv.x + bv.x;
    ov.y = (xv.y - mu) * rs * gv.y + bv.y;
    ov.z = (xv.z - mu) * rs * gv.z + bv.z;
    ov.w = (xv.w - mu) * rs * gv.w + bv.w;
    *(float4*)(out + (size_t)row * 1024 + tid * 4) = ov;
}

// ===========================================================================
extern "C" void kernel_launch(void* const* d_in, const int* in_sizes, int n_in,
                              void* d_out, int out_size)
{
    const float* Q  = (const float*)d_in[0];
    const float* K  = (const float*)d_in[1];
    const float* Wq = (const float*)d_in[2];
    const float* bq = (const float*)d_in[3];
    const float* Wk = (const float*)d_in[4];
    const float* bk = (const float*)d_in[5];
    const float* Wv = (const float*)d_in[6];
    const float* bv = (const float*)d_in[7];
    const float* Wo = (const float*)d_in[8];
    const float* bo = (const float*)d_in[9];
    const float* g0 = (const float*)d_in[10];
    const float* b0 = (const float*)d_in[11];
    const float* g1 = (const float*)d_in[12];
    const float* b1 = (const float*)d_in[13];
    float* out = (float*)d_out;

    float *qp, *kp, *vp, *xp, *yp;
    uint4 *apk, *wpk, *qpk, *kpk, *vpk;
    cudaGetSymbolAddress((void**)&qp,  g_q);
    cudaGetSymbolAddress((void**)&kp,  g_k);
    cudaGetSymbolAddress((void**)&vp,  g_v);
    cudaGetSymbolAddress((void**)&xp,  g_x);
    cudaGetSymbolAddress((void**)&yp,  g_y);
    cudaGetSymbolAddress((void**)&apk, g_apk);
    cudaGetSymbolAddress((void**)&wpk, g_wpk);
    cudaGetSymbolAddress((void**)&qpk, g_qpk);
    cudaGetSymbolAddress((void**)&kpk, g_kpk);
    cudaGetSymbolAddress((void**)&vpk, g_vpk);

    cudaFuncSetAttribute(gemm_f16_kernel,
                         cudaFuncAttributeMaxDynamicSharedMemorySize, G16_SMEM_BYTES);
    cudaFuncSetAttribute(attn5_kernel,
                         cudaFuncAttributeMaxDynamicSharedMemorySize, ATT5_SMEM_BYTES);

    // pack weights (fp16 B-frags)
    pack_w_kernel<<<512, 256>>>(Wq, wpk + 0 * 131072);
    pack_w_kernel<<<512, 256>>>(Wk, wpk + 1 * 131072);
    pack_w_kernel<<<512, 256>>>(Wv, wpk + 2 * 131072);
    pack_w_kernel<<<512, 256>>>(Wo, wpk + 3 * 131072);

    // q projection: pack A(Q), gemm -> qp (fp32)
    pack_a_kernel<<<4096, 256>>>(Q, apk);
    gemm_f16_kernel<<<dim3(8, 64), 256, G16_SMEM_BYTES>>>(apk, wpk + 0 * 131072, bq, nullptr, qp, 0);
    // k/v projections: pack A(K) once
    pack_a_kernel<<<8192, 256>>>(K, apk);
    gemm_f16_kernel<<<dim3(8, 128), 256, G16_SMEM_BYTES>>>(apk, wpk + 1 * 131072, bk, nullptr, kp, 0);
    gemm_f16_kernel<<<dim3(8, 128), 256, G16_SMEM_BYTES>>>(apk, wpk + 2 * 131072, bv, nullptr, vp, 0);

    // pack attention operands (fp32 -> fp16 frags)
    pack_q_kernel<<<4096, 256>>>(qp, qpk);
    pack_k_kernel<<<8192, 256>>>(kp, kpk);
    pack_v_kernel<<<8192, 256>>>(vp, vpk);

    // attention + residual
    attn5_kernel<<<dim3(16, CH, CB), 256, ATT5_SMEM_BYTES>>>(qpk, qp, kpk, vpk, xp);
    // LN0 (in place)
    ln_kernel<<<CB * CNQ, 256>>>(xp, xp, g0, b0);
    // y = x + relu(x @ Wo + bo)
    pack_a_kernel<<<4096, 256>>>(xp, apk);
    gemm_f16_kernel<<<dim3(8, 64), 256, G16_SMEM_BYTES>>>(apk, wpk + 3 * 131072, bo, xp, yp, 1);
    // LN1 -> out
    ln_kernel<<<CB * CNQ, 256>>>(yp, out, g1, b1);
}

// round 16
// speedup vs baseline: 6.0773x; 1.0799x over previous
#include <cuda_runtime.h>
#include <cuda_fp16.h>
#include <math.h>
#include <stddef.h>
#include <stdint.h>

static constexpr int CB  = 8;     // batch
static constexpr int CNQ = 1024;  // query tokens
static constexpr int CNK = 2048;  // key tokens
static constexpr int CD  = 1024;  // model dim
static constexpr int CH  = 8;     // heads
static constexpr int CDH = 128;   // head dim

// ---------------- scratch (no allocations allowed -> device globals) -------
__device__ float g_q[CB * CNQ * CD];    // q projection (fp32 exact, residual)
__device__ float g_x[CB * CNQ * CD];    // attn out / LN0 out
__device__ float g_y[CB * CNQ * CD];    // pre-LN1
__device__ uint4 g_apk[2097152];        // GEMM A packed (fp16 frags)
__device__ uint4 g_wpk[4][131072];      // weights packed (fp16 B-frags)
__device__ uint4 g_qpk[1048576];        // attn Q packed (A-frags)
__device__ uint4 g_kpk[2097152];        // attn K packed (S B-frags)
__device__ uint4 g_vpk[2097152];        // attn V packed (PV B-frags)

__device__ __forceinline__ uint32_t f2h2(float a, float b) {
    __half2 h = __floats2half2_rn(a, b);
    return *reinterpret_cast<uint32_t*>(&h);
}
__device__ __forceinline__ uint32_t h2u(__half a, __half b) {
    __half2 h = __halves2half2(a, b);
    return *reinterpret_cast<uint32_t*>(&h);
}

__device__ __forceinline__ uint32_t smem_u32(const void* p) {
    uint32_t a;
    asm("{ .reg .u64 t; cvta.to.shared.u64 t, %1; cvt.u32.u64 %0, t; }"
        : "=r"(a) : "l"(p));
    return a;
}

__device__ __forceinline__ void cpasync16(uint32_t dst, const void* src) {
    asm volatile("cp.async.cg.shared.global [%0], [%1], 16;"
                 :: "r"(dst), "l"(src));
}
#define CP_COMMIT() asm volatile("cp.async.commit_group;" ::: "memory")
#define CP_WAIT(n)  asm volatile("cp.async.wait_group %0;" :: "n"(n) : "memory")

// fp16 mma: D(16x8,f32) += A(16x16,f16 row) * B(16x8,f16 col)
__device__ __forceinline__ void mma16816(float* c, uint4 a, uint32_t b0, uint32_t b1) {
    asm volatile(
        "mma.sync.aligned.m16n8k16.row.col.f32.f16.f16.f32 "
        "{%0,%1,%2,%3}, {%4,%5,%6,%7}, {%8,%9}, {%0,%1,%2,%3};"
        : "+f"(c[0]), "+f"(c[1]), "+f"(c[2]), "+f"(c[3])
        : "r"(a.x), "r"(a.y), "r"(a.z), "r"(a.w), "r"(b0), "r"(b1));
}

// ===========================================================================
// Packing kernels (A-operands and weights).
// m16n8k16 fragment layouts (lane = 4g + t):
//   A(16x16): R0={A[g][2t],A[g][2t+1]} R1={A[g+8][2t],+1} R2={A[g][2t+8],+9} R3={A[g+8][2t+8],+9}
//   B(16x8 col): R0={B[2t][g],B[2t+1][g]} R1={B[2t+8][g],B[2t+9][g]}
//   C(16x8 f32): c0=(g,2t) c1=(g,2t+1) c2=(g+8,2t) c3=(g+8,2t+1)
// ===========================================================================

__global__ __launch_bounds__(256)
void pack_a_kernel(const float* __restrict__ in, uint4* __restrict__ out)
{
    const int f = blockIdx.x * 256 + threadIdx.x;
    const int lane = f & 31, kc = (f >> 5) & 63, rt = f >> 11;
    const int g = lane >> 2, t = lane & 3;
    const float* r0 = in + (size_t)(rt * 16 + g) * CD + kc * 16 + 2 * t;
    const float* r8 = r0 + 8 * CD;
    uint4 o;
    o.x = f2h2(r0[0], r0[1]);
    o.y = f2h2(r8[0], r8[1]);
    o.z = f2h2(r0[8], r0[9]);
    o.w = f2h2(r8[8], r8[9]);
    out[f] = o;
}

__global__ __launch_bounds__(256)
void pack_w_kernel(const float* __restrict__ w, uint4* __restrict__ out)
{
    const int f = blockIdx.x * 256 + threadIdx.x;
    const int lane = f & 31, pair = (f >> 5) & 3, wn = (f >> 7) & 1;
    const int kc = (f >> 8) & 63, ct = f >> 14;
    const int g = lane >> 2, t = lane & 3;
    const int k0 = kc * 16 + 2 * t;
    const int c0 = ct * 128 + (wn * 8 + pair * 2) * 8 + g;
    const int c1 = c0 + 8;
    uint4 o;
    o.x = f2h2(w[(size_t)k0 * CD + c0],       w[(size_t)(k0 + 1) * CD + c0]);
    o.y = f2h2(w[(size_t)(k0 + 8) * CD + c0], w[(size_t)(k0 + 9) * CD + c0]);
    o.z = f2h2(w[(size_t)k0 * CD + c1],       w[(size_t)(k0 + 1) * CD + c1]);
    o.w = f2h2(w[(size_t)(k0 + 8) * CD + c1], w[(size_t)(k0 + 9) * CD + c1]);
    out[f] = o;
}

// ===========================================================================
// fp16 GEMM with fused epilogues.
// mode 0: C = acc + bias (fp32)
// mode 1: C = R + relu(acc + bias) (fp32)
// mode 2: QPACK  -> C fp32 + Opk (attn A-frag layout)
// mode 3: KPACK  -> Opk only (attn S B-frag layout)
// mode 4: VPACK  -> Opk only (attn PV B-frag layout, via smem transpose)
// ===========================================================================
static constexpr int G16_STAGES = 3;
static constexpr int G16_PIPE_BYTES = G16_STAGES * 512 * 16;           // 24576
static constexpr int G16_SMEM_BYTES = 128 * 136 * 2 > G16_PIPE_BYTES
                                      ? 128 * 136 * 2 : G16_PIPE_BYTES; // 34816

__global__ __launch_bounds__(256, 2)
void gemm_f16_kernel(const uint4* __restrict__ Apk, const uint4* __restrict__ Wpk,
                     const float* __restrict__ bias, const float* __restrict__ R,
                     float* __restrict__ C, uint4* __restrict__ Opk, int mode)
{
    extern __shared__ uint4 smu[];
    const int tid  = threadIdx.x;
    const int lane = tid & 31;
    const int w    = tid >> 5;
    const int wm   = w & 3;      // 32-row group
    const int wn   = w >> 2;     // 64-col group
    const int by   = blockIdx.y;
    const int rt0  = by * 8;     // rowtile base (16-row tiles)
    const int ct   = blockIdx.x; // 128-col tile (== head for k/v/q)

    const uint32_t sbase = smem_u32(smu);
    const int art = tid >> 5;

    float acc[2][8][4];
#pragma unroll
    for (int i = 0; i < 2; ++i)
#pragma unroll
        for (int n = 0; n < 8; ++n)
#pragma unroll
            for (int c = 0; c < 4; ++c) acc[i][n][c] = 0.f;

#pragma unroll
    for (int s = 0; s < G16_STAGES - 1; ++s) {
        cpasync16(sbase + (s * 512 + tid) * 16,
                  Apk + ((size_t)(rt0 + art) * 64 + s) * 32 + lane);
        cpasync16(sbase + (s * 512 + 256 + tid) * 16,
                  Wpk + ((size_t)ct * 64 + s) * 256 + tid);
        CP_COMMIT();
    }

    for (int kc = 0; kc < 64; ++kc) {
        CP_WAIT(1);
        __syncthreads();
        if (kc + 2 < 64) {
            const int s = (kc + 2) % G16_STAGES;
            cpasync16(sbase + (s * 512 + tid) * 16,
                      Apk + ((size_t)(rt0 + art) * 64 + kc + 2) * 32 + lane);
            cpasync16(sbase + (s * 512 + 256 + tid) * 16,
                      Wpk + ((size_t)ct * 64 + kc + 2) * 256 + tid);
        }
        CP_COMMIT();

        const uint4* As = smu + (kc % G16_STAGES) * 512;
        const uint4* Bs = As + 256;
        uint4 af[2];
#pragma unroll
        for (int i = 0; i < 2; ++i) af[i] = As[(2 * wm + i) * 32 + lane];
#pragma unroll
        for (int p = 0; p < 4; ++p) {
            uint4 bf = Bs[(wn * 4 + p) * 32 + lane];
#pragma unroll
            for (int i = 0; i < 2; ++i) {
                mma16816(acc[i][2 * p],     af[i], bf.x, bf.y);
                mma16816(acc[i][2 * p + 1], af[i], bf.z, bf.w);
            }
        }
    }
    CP_WAIT(0);

    const int g = lane >> 2, t = lane & 3;

    // bias add (all modes)
#pragma unroll
    for (int n = 0; n < 8; ++n) {
        const int col = ct * 128 + wn * 64 + n * 8 + 2 * t;
        float2 bb = *(const float2*)(bias + col);
#pragma unroll
        for (int i = 0; i < 2; ++i) {
            acc[i][n][0] += bb.x; acc[i][n][1] += bb.y;
            acc[i][n][2] += bb.x; acc[i][n][3] += bb.y;
        }
    }

    if (mode <= 2) {
        // fp32 out (mode 1: + relu residual)
#pragma unroll
        for (int i = 0; i < 2; ++i) {
            const int r = by * 128 + wm * 32 + i * 16 + g;
#pragma unroll
            for (int n = 0; n < 8; ++n) {
                const int col = ct * 128 + wn * 64 + n * 8 + 2 * t;
                float2 v0 = {acc[i][n][0], acc[i][n][1]};
                float2 v8 = {acc[i][n][2], acc[i][n][3]};
                if (mode == 1) {
                    float2 r0 = *(const float2*)(R + (size_t)r * CD + col);
                    float2 r8 = *(const float2*)(R + (size_t)(r + 8) * CD + col);
                    v0.x = r0.x + fmaxf(v0.x, 0.f); v0.y = r0.y + fmaxf(v0.y, 0.f);
                    v8.x = r8.x + fmaxf(v8.x, 0.f); v8.y = r8.y + fmaxf(v8.y, 0.f);
                }
                *(float2*)(C + (size_t)r * CD + col)       = v0;
                *(float2*)(C + (size_t)(r + 8) * CD + col) = v8;
            }
        }
    }

    if (mode == 2) {
        // QPACK: attn A-frag layout [b][tile16][h][wr4][kc8][lane]
#pragma unroll
        for (int i = 0; i < 2; ++i) {
            const int rowbase = by * 128 + wm * 32 + i * 16;
            const int b    = rowbase >> 10;
            const int rin  = rowbase & 1023;
            const int tile = rin >> 6;
            const int wr   = (rin >> 4) & 3;
            const size_t base = (((size_t)(b * 16 + tile) * 8 + ct) << 10) + wr * 8 * 32;
#pragma unroll
            for (int p = 0; p < 4; ++p) {
                const int kc = wn * 4 + p;
                uint4 o;
                o.x = f2h2(acc[i][2 * p][0],     acc[i][2 * p][1]);
                o.y = f2h2(acc[i][2 * p][2],     acc[i][2 * p][3]);
                o.z = f2h2(acc[i][2 * p + 1][0], acc[i][2 * p + 1][1]);
                o.w = f2h2(acc[i][2 * p + 1][2], acc[i][2 * p + 1][3]);
                Opk[base + kc * 32 + lane] = o;
            }
        }
    } else if (mode == 3) {
        // KPACK: attn S B-frag layout [b][h][kt32][kc8][wc2][pair2][lane]
#pragma unroll
        for (int i = 0; i < 2; ++i) {
            const int rowbase = by * 128 + wm * 32 + i * 16;
            const int b  = rowbase >> 11;
            const int kt = (rowbase & 2047) >> 6;
            const int q_ = (rowbase >> 4) & 3;
            const size_t base = (((size_t)(b * 8 + ct)) << 15) + (size_t)kt * 1024
                              + ((q_ >> 1) * 2 + (q_ & 1)) * 32;
#pragma unroll
            for (int p = 0; p < 4; ++p) {
                const int kc = wn * 4 + p;
                uint4 o;
                o.x = f2h2(acc[i][2 * p][0],     acc[i][2 * p][1]);
                o.y = f2h2(acc[i][2 * p + 1][0], acc[i][2 * p + 1][1]);
                o.z = f2h2(acc[i][2 * p][2],     acc[i][2 * p][3]);
                o.w = f2h2(acc[i][2 * p + 1][2], acc[i][2 * p + 1][3]);
                Opk[base + kc * 4 * 32 + lane] = o;
            }
        }
    } else if (mode == 4) {
        // VPACK: stage fp16 tile in smem (token-major), then emit B-frags.
        __syncthreads();                       // pipeline smem reads done
        __half* VT = (__half*)smu;             // [128][136]
#pragma unroll
        for (int i = 0; i < 2; ++i) {
            const int rl = wm * 32 + i * 16 + g;
#pragma unroll
            for (int n = 0; n < 8; ++n) {
                const int cl = wn * 64 + n * 8 + 2 * t;
                *(uint32_t*)&VT[rl * 136 + cl]       = f2h2(acc[i][n][0], acc[i][n][1]);
                *(uint32_t*)&VT[(rl + 8) * 136 + cl] = f2h2(acc[i][n][2], acc[i][n][3]);
            }
        }
        __syncthreads();
        const int b = by >> 4;                 // 16 row-blocks (2048 tokens) per batch
#pragma unroll
        for (int u = 0; u < 8; ++u) {
            const int f = tid + u * 256;       // 0..2047
            const int kt_l  = f >> 10;
            const int rest  = f & 1023;
            const int jc    = (rest >> 8) & 3;
            const int wcd   = (rest >> 7) & 1;
            const int pair  = (rest >> 5) & 3;
            const int ln    = rest & 31;
            const int go    = ln >> 2, to = ln & 3;
            const int j0 = kt_l * 64 + jc * 16 + 2 * to;
            const int d0 = (wcd * 8 + pair * 2) * 8 + go;
            uint4 o;
            o.x = h2u(VT[j0 * 136 + d0],       VT[(j0 + 1) * 136 + d0]);
            o.y = h2u(VT[(j0 + 8) * 136 + d0], VT[(j0 + 9) * 136 + d0]);
            o.z = h2u(VT[j0 * 136 + d0 + 8],       VT[(j0 + 1) * 136 + d0 + 8]);
            o.w = h2u(VT[(j0 + 8) * 136 + d0 + 8], VT[(j0 + 9) * 136 + d0 + 8]);
            const int kt_g = (by & 15) * 2 + kt_l;   // FIX: tile index within batch
            Opk[(((size_t)(b * 8 + ct)) << 15) + (size_t)kt_g * 1024
                + ((jc * 2 + wcd) * 4 + pair) * 32 + ln] = o;
        }
    }
}

// ===========================================================================
// Attention v5 (unchanged from R13).
// ===========================================================================
static constexpr int ATT5_SMEM_BYTES = 5120 * 16 + 128 * 4;   // 82432

__global__ __launch_bounds__(256, 2)
void attn5_kernel(const uint4* __restrict__ qpk, const float* __restrict__ qe,
                  const uint4* __restrict__ kpk, const uint4* __restrict__ vpk,
                  float* __restrict__ x)
{
    extern __shared__ uint4 smu[];
    const uint4* Qs = smu;
    float* lrow2 = (float*)(smu + 5120);
    float* stg   = (float*)(smu + 3072);

    const int b    = blockIdx.z;
    const int h    = blockIdx.y;
    const int tile = blockIdx.x;
    const int tid  = threadIdx.x;
    const int lane = tid & 31;
    const int w    = tid >> 5;
    const int wr   = w & 3;
    const int wc   = w >> 2;
    const int g    = lane >> 2, t = lane & 3;

    const uint4* qsrc  = qpk + (((size_t)(b * 16 + tile) * 8 + h) << 10);
    const uint4* kbase = kpk + (((size_t)(b * 8 + h)) << 15);
    const uint4* vbase = vpk + (((size_t)(b * 8 + h)) << 15);
    const float* qeb = qe + ((size_t)(b * CNQ + tile * 64)) * CD + h * CDH;
    float*       xb  = x  + ((size_t)(b * CNQ + tile * 64)) * CD + h * CDH;

    const uint32_t sb = smem_u32(smu);

#pragma unroll
    for (int u = 0; u < 4; ++u)
        cpasync16(sb + (tid + u * 256) * 16, qsrc + tid + u * 256);
#pragma unroll
    for (int u = 0; u < 4; ++u)
        cpasync16(sb + (1024 + tid + u * 256) * 16, kbase + tid + u * 256);
#pragma unroll
    for (int u = 0; u < 4; ++u)
        cpasync16(sb + (3072 + tid + u * 256) * 16, vbase + tid + u * 256);
    CP_COMMIT();

    if (tid < 128) lrow2[tid] = 0.f;

    float oacc[16][4];
#pragma unroll
    for (int n = 0; n < 16; ++n)
#pragma unroll
        for (int c = 0; c < 4; ++c) oacc[n][c] = 0.f;

    const float scale = 0.03125f;

    CP_WAIT(0);
    __syncthreads();

    for (int kt = 0; kt < 32; ++kt) {
        const int cur = kt & 1;
        if (kt + 1 < 32) {
            const int nxt = 1 - cur;
            const uint4* ks = kbase + ((size_t)(kt + 1) << 10);
            const uint4* vs = vbase + ((size_t)(kt + 1) << 10);
#pragma unroll
            for (int u = 0; u < 4; ++u)
                cpasync16(sb + (1024 + nxt * 1024 + tid + u * 256) * 16, ks + tid + u * 256);
#pragma unroll
            for (int u = 0; u < 4; ++u)
                cpasync16(sb + (3072 + nxt * 1024 + tid + u * 256) * 16, vs + tid + u * 256);
            CP_COMMIT();
        }

        const uint4* Ks = smu + 1024 + cur * 1024;
        const uint4* Vs = smu + 3072 + cur * 1024;

        float sacc[4][4];
#pragma unroll
        for (int n = 0; n < 4; ++n)
#pragma unroll
            for (int c = 0; c < 4; ++c) sacc[n][c] = 0.f;
#pragma unroll
        for (int kc = 0; kc < 8; ++kc) {
            uint4 qf = Qs[(wr * 8 + kc) * 32 + lane];
#pragma unroll
            for (int p = 0; p < 2; ++p) {
                uint4 kf = Ks[((kc * 2 + wc) * 2 + p) * 32 + lane];
                mma16816(sacc[2 * p],     qf, kf.x, kf.y);
                mma16816(sacc[2 * p + 1], qf, kf.z, kf.w);
            }
        }

        float e[4][4];
        float sum0 = 0.f, sum1 = 0.f;
#pragma unroll
        for (int n = 0; n < 4; ++n)
#pragma unroll
            for (int c = 0; c < 4; ++c) {
                e[n][c] = __expf(sacc[n][c] * scale);
                if (c < 2) sum0 += e[n][c]; else sum1 += e[n][c];
            }
        sum0 += __shfl_xor_sync(0xffffffffu, sum0, 1);
        sum0 += __shfl_xor_sync(0xffffffffu, sum0, 2);
        sum1 += __shfl_xor_sync(0xffffffffu, sum1, 1);
        sum1 += __shfl_xor_sync(0xffffffffu, sum1, 2);
        if (t == 0) {
            const int r = wr * 16 + g;
            lrow2[wc * 64 + r]     += sum0;
            lrow2[wc * 64 + r + 8] += sum1;
        }
        uint4 pf[2];
        pf[0].x = f2h2(e[0][0], e[0][1]); pf[0].y = f2h2(e[0][2], e[0][3]);
        pf[0].z = f2h2(e[1][0], e[1][1]); pf[0].w = f2h2(e[1][2], e[1][3]);
        pf[1].x = f2h2(e[2][0], e[2][1]); pf[1].y = f2h2(e[2][2], e[2][3]);
        pf[1].z = f2h2(e[3][0], e[3][1]); pf[1].w = f2h2(e[3][2], e[3][3]);

#pragma unroll
        for (int J = 0; J < 2; ++J) {
            const int jc = wc * 2 + J;
#pragma unroll
            for (int wcd = 0; wcd < 2; ++wcd)
#pragma unroll
                for (int p = 0; p < 4; ++p) {
                    uint4 vf = Vs[((jc * 2 + wcd) * 4 + p) * 32 + lane];
                    const int n = wcd * 8 + p * 2;
                    mma16816(oacc[n],     pf[J], vf.x, vf.y);
                    mma16816(oacc[n + 1], pf[J], vf.z, vf.w);
                }
        }

        CP_WAIT(0);
        __syncthreads();
    }

    {
        const int r = wr * 16 + g;
#pragma unroll
        for (int n = (1 - wc) * 8; n < (1 - wc) * 8 + 8; ++n) {
            const int d = n * 8 + 2 * t;
            stg[r * 128 + d]           = oacc[n][0];
            stg[r * 128 + d + 1]       = oacc[n][1];
            stg[(r + 8) * 128 + d]     = oacc[n][2];
            stg[(r + 8) * 128 + d + 1] = oacc[n][3];
        }
    }
    __syncthreads();
    {
        const int r = wr * 16 + g;
        const float inv0 = 1.f / (lrow2[r] + lrow2[64 + r]);
        const float inv8 = 1.f / (lrow2[r + 8] + lrow2[64 + r + 8]);
#pragma unroll
        for (int n = wc * 8; n < wc * 8 + 8; ++n) {
            const int d = n * 8 + 2 * t;
            float2 q0 = *(const float2*)(qeb + (size_t)r * CD + d);
            float2 q8 = *(const float2*)(qeb + (size_t)(r + 8) * CD + d);
            float2 o0, o8;
            o0.x = fmaf(oacc[n][0] + stg[r * 128 + d],           inv0, q0.x);
            o0.y = fmaf(oacc[n][1] + stg[r * 128 + d + 1],       inv0, q0.y);
            o8.x = fmaf(oacc[n][2] + stg[(r + 8) * 128 + d],     inv8, q8.x);
            o8.y = fmaf(oacc[n][3] + stg[(r + 8) * 128 + d + 1], inv8, q8.y);
            *(float2*)(xb + (size_t)r * CD + d)       = o0;
            *(float2*)(xb + (size_t)(r + 8) * CD + d) = o8;
        }
    }
}

// ===========================================================================
// Row LayerNorm over 1024 columns.
// ===========================================================================
__global__ __launch_bounds__(256)
void ln_kernel(const float* __restrict__ in, float* __restrict__ out,
               const float* __restrict__ g, const float* __restrict__ bta)
{
    __shared__ float red_s[8], red_s2[8];
    __shared__ float mu_s, rs_s;
    const int row = blockIdx.x;
    const int tid = threadIdx.x;
    const float* rp = in + (size_t)row * 1024;

    float4 xv = *(const float4*)(rp + tid * 4);
    float s  = xv.x + xv.y + xv.z + xv.w;
    float s2 = xv.x * xv.x + xv.y * xv.y + xv.z * xv.z + xv.w * xv.w;
#pragma unroll
    for (int off = 16; off >= 1; off >>= 1) {
        s  += __shfl_xor_sync(0xffffffffu, s,  off);
        s2 += __shfl_xor_sync(0xffffffffu, s2, off);
    }
    if ((tid & 31) == 0) { red_s[tid >> 5] = s; red_s2[tid >> 5] = s2; }
    __syncthreads();
    if (tid == 0) {
        float a = 0.f, a2 = 0.f;
#pragma unroll
        for (int wq = 0; wq < 8; ++wq) { a += red_s[wq]; a2 += red_s2[wq]; }
        const float mu  = a * (1.f / 1024.f);
        const float var = a2 * (1.f / 1024.f) - mu * mu;
        mu_s = mu;
        rs_s = rsqrtf(var + 1e-5f);
    }
    __syncthreads();
    const float mu = mu_s, rs = rs_s;
    float4 gv = *(const float4*)(g + tid * 4);
    float4 bv = *(const float4*)(bta + tid * 4);
    float4 ov;
    ov.x = (xv.x - mu) * rs * gv.x + bv.x;
    ov.y = (xv.y - mu) * rs * gv.y + bv.y;
    ov.z = (xv.z - mu) * rs * gv.z + bv.z;
    ov.w = (xv.w - mu) * rs * gv.w + bv.w;
    *(float4*)(out + (size_t)row * 1024 + tid * 4) = ov;
}

// ===========================================================================
extern "C" void kernel_launch(void* const* d_in, const int* in_sizes, int n_in,
                              void* d_out, int out_size)
{
    const float* Q  = (const float*)d_in[0];
    const float* K  = (const float*)d_in[1];
    const float* Wq = (const float*)d_in[2];
    const float* bq = (const float*)d_in[3];
    const float* Wk = (const float*)d_in[4];
    const float* bk = (const float*)d_in[5];
    const float* Wv = (const float*)d_in[6];
    const float* bv = (const float*)d_in[7];
    const float* Wo = (const float*)d_in[8];
    const float* bo = (const float*)d_in[9];
    const float* g0 = (const float*)d_in[10];
    const float* b0 = (const float*)d_in[11];
    const float* g1 = (const float*)d_in[12];
    const float* b1 = (const float*)d_in[13];
    float* out = (float*)d_out;

    float *qp, *xp, *yp;
    uint4 *apk, *wpk, *qpk, *kpk, *vpk;
    cudaGetSymbolAddress((void**)&qp,  g_q);
    cudaGetSymbolAddress((void**)&xp,  g_x);
    cudaGetSymbolAddress((void**)&yp,  g_y);
    cudaGetSymbolAddress((void**)&apk, g_apk);
    cudaGetSymbolAddress((void**)&wpk, g_wpk);
    cudaGetSymbolAddress((void**)&qpk, g_qpk);
    cudaGetSymbolAddress((void**)&kpk, g_kpk);
    cudaGetSymbolAddress((void**)&vpk, g_vpk);

    cudaFuncSetAttribute(gemm_f16_kernel,
                         cudaFuncAttributeMaxDynamicSharedMemorySize, G16_SMEM_BYTES);
    cudaFuncSetAttribute(attn5_kernel,
                         cudaFuncAttributeMaxDynamicSharedMemorySize, ATT5_SMEM_BYTES);

    // pack weights
    pack_w_kernel<<<512, 256>>>(Wq, wpk + 0 * 131072);
    pack_w_kernel<<<512, 256>>>(Wk, wpk + 1 * 131072);
    pack_w_kernel<<<512, 256>>>(Wv, wpk + 2 * 131072);
    pack_w_kernel<<<512, 256>>>(Wo, wpk + 3 * 131072);

    // q projection: fp32 (residual) + packed A-frags, fused
    pack_a_kernel<<<4096, 256>>>(Q, apk);
    gemm_f16_kernel<<<dim3(8, 64), 256, G16_SMEM_BYTES>>>(
        apk, wpk + 0 * 131072, bq, nullptr, qp, qpk, 2);
    // k/v projections: packed-only outputs, fused
    pack_a_kernel<<<8192, 256>>>(K, apk);
    gemm_f16_kernel<<<dim3(8, 128), 256, G16_SMEM_BYTES>>>(
        apk, wpk + 1 * 131072, bk, nullptr, nullptr, kpk, 3);
    gemm_f16_kernel<<<dim3(8, 128), 256, G16_SMEM_BYTES>>>(
        apk, wpk + 2 * 131072, bv, nullptr, nullptr, vpk, 4);

    // attention + residual
    attn5_kernel<<<dim3(16, CH, CB), 256, ATT5_SMEM_BYTES>>>(qpk, qp, kpk, vpk, xp);
    // LN0 (in place)
    ln_kernel<<<CB * CNQ, 256>>>(xp, xp, g0, b0);
    // y = x + relu(x @ Wo + bo)
    pack_a_kernel<<<4096, 256>>>(xp, apk);
    gemm_f16_kernel<<<dim3(8, 64), 256, G16_SMEM_BYTES>>>(
        apk, wpk + 3 * 131072, bo, xp, yp, nullptr, 1);
    // LN1 -> out
    ln_kernel<<<CB * CNQ, 256>>>(yp, out, g1, b1);
}

// round 17
// speedup vs baseline: 6.2790x; 1.0332x over previous
#include <cuda_runtime.h>
#include <cuda_fp16.h>
#include <math.h>
#include <stddef.h>
#include <stdint.h>

static constexpr int CB  = 8;     // batch
static constexpr int CNQ = 1024;  // query tokens
static constexpr int CNK = 2048;  // key tokens
static constexpr int CD  = 1024;  // model dim
static constexpr int CH  = 8;     // heads
static constexpr int CDH = 128;   // head dim

// ---------------- scratch (no allocations allowed -> device globals) -------
__device__ float g_q[CB * CNQ * CD];    // q projection (fp32 exact, residual)
__device__ float g_x[CB * CNQ * CD];    // attn out / LN0 out
__device__ float g_y[CB * CNQ * CD];    // pre-LN1
__device__ uint4 g_apq[1048576];        // A packed: Q input / LN0 out (16 MB)
__device__ uint4 g_apk[2097152];        // A packed: K input (32 MB)
__device__ uint4 g_wpk[4][131072];      // weights packed (fp16 B-frags)
__device__ uint4 g_qpk[1048576];        // attn Q packed (A-frags)
__device__ uint4 g_kpk[2097152];        // attn K packed (S B-frags)
__device__ uint4 g_vpk[2097152];        // attn V packed (PV B-frags)

__device__ __forceinline__ uint32_t f2h2(float a, float b) {
    __half2 h = __floats2half2_rn(a, b);
    return *reinterpret_cast<uint32_t*>(&h);
}
__device__ __forceinline__ uint32_t h2u(__half a, __half b) {
    __half2 h = __halves2half2(a, b);
    return *reinterpret_cast<uint32_t*>(&h);
}

__device__ __forceinline__ uint32_t smem_u32(const void* p) {
    uint32_t a;
    asm("{ .reg .u64 t; cvta.to.shared.u64 t, %1; cvt.u32.u64 %0, t; }"
        : "=r"(a) : "l"(p));
    return a;
}

__device__ __forceinline__ void cpasync16(uint32_t dst, const void* src) {
    asm volatile("cp.async.cg.shared.global [%0], [%1], 16;"
                 :: "r"(dst), "l"(src));
}
#define CP_COMMIT() asm volatile("cp.async.commit_group;" ::: "memory")
#define CP_WAIT(n)  asm volatile("cp.async.wait_group %0;" :: "n"(n) : "memory")

// fp16 mma: D(16x8,f32) += A(16x16,f16 row) * B(16x8,f16 col)
__device__ __forceinline__ void mma16816(float* c, uint4 a, uint32_t b0, uint32_t b1) {
    asm volatile(
        "mma.sync.aligned.m16n8k16.row.col.f32.f16.f16.f32 "
        "{%0,%1,%2,%3}, {%4,%5,%6,%7}, {%8,%9}, {%0,%1,%2,%3};"
        : "+f"(c[0]), "+f"(c[1]), "+f"(c[2]), "+f"(c[3])
        : "r"(a.x), "r"(a.y), "r"(a.z), "r"(a.w), "r"(b0), "r"(b1));
}

// ===========================================================================
// Packing kernels (merged launches).
// m16n8k16 fragment layouts (lane = 4g + t):
//   A(16x16): R0={A[g][2t],A[g][2t+1]} R1={A[g+8][2t],+1} R2={A[g][2t+8],+9} R3={A[g+8][2t+8],+9}
//   B(16x8 col): R0={B[2t][g],B[2t+1][g]} R1={B[2t+8][g],B[2t+9][g]}
//   C(16x8 f32): c0=(g,2t) c1=(g,2t+1) c2=(g+8,2t) c3=(g+8,2t+1)
// ===========================================================================

// Q (4096 blocks) then K (8192 blocks) in one launch
__global__ __launch_bounds__(256)
void pack_a_all_kernel(const float* __restrict__ Q, const float* __restrict__ K,
                       uint4* __restrict__ outQ, uint4* __restrict__ outK)
{
    const bool isQ = blockIdx.x < 4096;
    const int f = (isQ ? blockIdx.x : blockIdx.x - 4096) * 256 + threadIdx.x;
    const float* in = isQ ? Q : K;
    uint4* out = isQ ? outQ : outK;
    const int lane = f & 31, kc = (f >> 5) & 63, rt = f >> 11;
    const int g = lane >> 2, t = lane & 3;
    const float* r0 = in + (size_t)(rt * 16 + g) * CD + kc * 16 + 2 * t;
    const float* r8 = r0 + 8 * CD;
    uint4 o;
    o.x = f2h2(r0[0], r0[1]);
    o.y = f2h2(r8[0], r8[1]);
    o.z = f2h2(r0[8], r0[9]);
    o.w = f2h2(r8[8], r8[9]);
    out[f] = o;
}

// all 4 weights in one launch: grid 2048 blocks (512 per weight)
__global__ __launch_bounds__(256)
void pack_w_all_kernel(const float* __restrict__ w0, const float* __restrict__ w1,
                       const float* __restrict__ w2, const float* __restrict__ w3,
                       uint4* __restrict__ out)   // -> g_wpk[widx]
{
    const int widx = blockIdx.x >> 9;
    const int f = (blockIdx.x & 511) * 256 + threadIdx.x;
    const float* w = widx == 0 ? w0 : widx == 1 ? w1 : widx == 2 ? w2 : w3;
    const int lane = f & 31, pair = (f >> 5) & 3, wn = (f >> 7) & 1;
    const int kc = (f >> 8) & 63, ct = f >> 14;
    const int g = lane >> 2, t = lane & 3;
    const int k0 = kc * 16 + 2 * t;
    const int c0 = ct * 128 + (wn * 8 + pair * 2) * 8 + g;
    const int c1 = c0 + 8;
    uint4 o;
    o.x = f2h2(w[(size_t)k0 * CD + c0],       w[(size_t)(k0 + 1) * CD + c0]);
    o.y = f2h2(w[(size_t)(k0 + 8) * CD + c0], w[(size_t)(k0 + 9) * CD + c0]);
    o.z = f2h2(w[(size_t)k0 * CD + c1],       w[(size_t)(k0 + 1) * CD + c1]);
    o.w = f2h2(w[(size_t)(k0 + 8) * CD + c1], w[(size_t)(k0 + 9) * CD + c1]);
    out[(size_t)widx * 131072 + f] = o;
}

// ===========================================================================
// fp16 GEMM core with fused epilogues.
// mode 1: C = R + relu(acc + bias) (fp32)
// mode 2: QPACK  -> C fp32 + Opk (attn A-frag layout)
// mode 3: KPACK  -> Opk only (attn S B-frag layout)
// mode 4: VPACK  -> Opk only (attn PV B-frag layout, via smem transpose)
// ===========================================================================
static constexpr int G16_STAGES = 3;
static constexpr int G16_PIPE_BYTES = G16_STAGES * 512 * 16;           // 24576
static constexpr int G16_SMEM_BYTES = 128 * 136 * 2 > G16_PIPE_BYTES
                                      ? 128 * 136 * 2 : G16_PIPE_BYTES; // 34816

__device__ __forceinline__
void gemm_core(const uint4* __restrict__ Apk, const uint4* __restrict__ Wpk,
               const float* __restrict__ bias, const float* __restrict__ R,
               float* __restrict__ C, uint4* __restrict__ Opk, int mode,
               int by, int ct, uint4* smu)
{
    const int tid  = threadIdx.x;
    const int lane = tid & 31;
    const int w    = tid >> 5;
    const int wm   = w & 3;
    const int wn   = w >> 2;
    const int rt0  = by * 8;

    const uint32_t sbase = smem_u32(smu);
    const int art = tid >> 5;

    float acc[2][8][4];
#pragma unroll
    for (int i = 0; i < 2; ++i)
#pragma unroll
        for (int n = 0; n < 8; ++n)
#pragma unroll
            for (int c = 0; c < 4; ++c) acc[i][n][c] = 0.f;

#pragma unroll
    for (int s = 0; s < G16_STAGES - 1; ++s) {
        cpasync16(sbase + (s * 512 + tid) * 16,
                  Apk + ((size_t)(rt0 + art) * 64 + s) * 32 + lane);
        cpasync16(sbase + (s * 512 + 256 + tid) * 16,
                  Wpk + ((size_t)ct * 64 + s) * 256 + tid);
        CP_COMMIT();
    }

    for (int kc = 0; kc < 64; ++kc) {
        CP_WAIT(1);
        __syncthreads();
        if (kc + 2 < 64) {
            const int s = (kc + 2) % G16_STAGES;
            cpasync16(sbase + (s * 512 + tid) * 16,
                      Apk + ((size_t)(rt0 + art) * 64 + kc + 2) * 32 + lane);
            cpasync16(sbase + (s * 512 + 256 + tid) * 16,
                      Wpk + ((size_t)ct * 64 + kc + 2) * 256 + tid);
        }
        CP_COMMIT();

        const uint4* As = smu + (kc % G16_STAGES) * 512;
        const uint4* Bs = As + 256;
        uint4 af[2];
#pragma unroll
        for (int i = 0; i < 2; ++i) af[i] = As[(2 * wm + i) * 32 + lane];
#pragma unroll
        for (int p = 0; p < 4; ++p) {
            uint4 bf = Bs[(wn * 4 + p) * 32 + lane];
#pragma unroll
            for (int i = 0; i < 2; ++i) {
                mma16816(acc[i][2 * p],     af[i], bf.x, bf.y);
                mma16816(acc[i][2 * p + 1], af[i], bf.z, bf.w);
            }
        }
    }
    CP_WAIT(0);

    const int g = lane >> 2, t = lane & 3;

#pragma unroll
    for (int n = 0; n < 8; ++n) {
        const int col = ct * 128 + wn * 64 + n * 8 + 2 * t;
        float2 bb = *(const float2*)(bias + col);
#pragma unroll
        for (int i = 0; i < 2; ++i) {
            acc[i][n][0] += bb.x; acc[i][n][1] += bb.y;
            acc[i][n][2] += bb.x; acc[i][n][3] += bb.y;
        }
    }

    if (mode <= 2) {
#pragma unroll
        for (int i = 0; i < 2; ++i) {
            const int r = by * 128 + wm * 32 + i * 16 + g;
#pragma unroll
            for (int n = 0; n < 8; ++n) {
                const int col = ct * 128 + wn * 64 + n * 8 + 2 * t;
                float2 v0 = {acc[i][n][0], acc[i][n][1]};
                float2 v8 = {acc[i][n][2], acc[i][n][3]};
                if (mode == 1) {
                    float2 r0 = *(const float2*)(R + (size_t)r * CD + col);
                    float2 r8 = *(const float2*)(R + (size_t)(r + 8) * CD + col);
                    v0.x = r0.x + fmaxf(v0.x, 0.f); v0.y = r0.y + fmaxf(v0.y, 0.f);
                    v8.x = r8.x + fmaxf(v8.x, 0.f); v8.y = r8.y + fmaxf(v8.y, 0.f);
                }
                *(float2*)(C + (size_t)r * CD + col)       = v0;
                *(float2*)(C + (size_t)(r + 8) * CD + col) = v8;
            }
        }
    }

    if (mode == 2) {
        // QPACK: attn A-frag layout [b][tile16][h][wr4][kc8][lane]
#pragma unroll
        for (int i = 0; i < 2; ++i) {
            const int rowbase = by * 128 + wm * 32 + i * 16;
            const int b    = rowbase >> 10;
            const int rin  = rowbase & 1023;
            const int tile = rin >> 6;
            const int wr   = (rin >> 4) & 3;
            const size_t base = (((size_t)(b * 16 + tile) * 8 + ct) << 10) + wr * 8 * 32;
#pragma unroll
            for (int p = 0; p < 4; ++p) {
                const int kc = wn * 4 + p;
                uint4 o;
                o.x = f2h2(acc[i][2 * p][0],     acc[i][2 * p][1]);
                o.y = f2h2(acc[i][2 * p][2],     acc[i][2 * p][3]);
                o.z = f2h2(acc[i][2 * p + 1][0], acc[i][2 * p + 1][1]);
                o.w = f2h2(acc[i][2 * p + 1][2], acc[i][2 * p + 1][3]);
                Opk[base + kc * 32 + lane] = o;
            }
        }
    } else if (mode == 3) {
        // KPACK: attn S B-frag layout [b][h][kt32][kc8][wc2][pair2][lane]
#pragma unroll
        for (int i = 0; i < 2; ++i) {
            const int rowbase = by * 128 + wm * 32 + i * 16;
            const int b  = rowbase >> 11;
            const int kt = (rowbase & 2047) >> 6;
            const int q_ = (rowbase >> 4) & 3;
            const size_t base = (((size_t)(b * 8 + ct)) << 15) + (size_t)kt * 1024
                              + ((q_ >> 1) * 2 + (q_ & 1)) * 32;
#pragma unroll
            for (int p = 0; p < 4; ++p) {
                const int kc = wn * 4 + p;
                uint4 o;
                o.x = f2h2(acc[i][2 * p][0],     acc[i][2 * p][1]);
                o.y = f2h2(acc[i][2 * p + 1][0], acc[i][2 * p + 1][1]);
                o.z = f2h2(acc[i][2 * p][2],     acc[i][2 * p][3]);
                o.w = f2h2(acc[i][2 * p + 1][2], acc[i][2 * p + 1][3]);
                Opk[base + kc * 4 * 32 + lane] = o;
            }
        }
    } else if (mode == 4) {
        // VPACK via smem transpose
        __syncthreads();
        __half* VT = (__half*)smu;             // [128][136]
#pragma unroll
        for (int i = 0; i < 2; ++i) {
            const int rl = wm * 32 + i * 16 + g;
#pragma unroll
            for (int n = 0; n < 8; ++n) {
                const int cl = wn * 64 + n * 8 + 2 * t;
                *(uint32_t*)&VT[rl * 136 + cl]       = f2h2(acc[i][n][0], acc[i][n][1]);
                *(uint32_t*)&VT[(rl + 8) * 136 + cl] = f2h2(acc[i][n][2], acc[i][n][3]);
            }
        }
        __syncthreads();
        const int b = by >> 4;
#pragma unroll
        for (int u = 0; u < 8; ++u) {
            const int f = tid + u * 256;
            const int kt_l  = f >> 10;
            const int rest  = f & 1023;
            const int jc    = (rest >> 8) & 3;
            const int wcd   = (rest >> 7) & 1;
            const int pair  = (rest >> 5) & 3;
            const int ln    = rest & 31;
            const int go    = ln >> 2, to = ln & 3;
            const int j0 = kt_l * 64 + jc * 16 + 2 * to;
            const int d0 = (wcd * 8 + pair * 2) * 8 + go;
            uint4 o;
            o.x = h2u(VT[j0 * 136 + d0],       VT[(j0 + 1) * 136 + d0]);
            o.y = h2u(VT[(j0 + 8) * 136 + d0], VT[(j0 + 9) * 136 + d0]);
            o.z = h2u(VT[j0 * 136 + d0 + 8],       VT[(j0 + 1) * 136 + d0 + 8]);
            o.w = h2u(VT[(j0 + 8) * 136 + d0 + 8], VT[(j0 + 9) * 136 + d0 + 8]);
            const int kt_g = (by & 15) * 2 + kt_l;
            Opk[(((size_t)(b * 8 + ct)) << 15) + (size_t)kt_g * 1024
                + ((jc * 2 + wcd) * 4 + pair) * 32 + ln] = o;
        }
    }
}

// merged q/k/v projection launch: z=0 q (by<64), z=1 k, z=2 v
__global__ __launch_bounds__(256, 2)
void gemm_proj_kernel(const uint4* __restrict__ apq, const uint4* __restrict__ apkk,
                      const uint4* __restrict__ wpk,
                      const float* __restrict__ bq, const float* __restrict__ bk,
                      const float* __restrict__ bv,
                      float* __restrict__ qp,
                      uint4* __restrict__ qpk, uint4* __restrict__ kpk,
                      uint4* __restrict__ vpk)
{
    extern __shared__ uint4 smu[];
    const int z = blockIdx.z;
    if (z == 0 && blockIdx.y >= 64) return;
    const uint4* Apk  = (z == 0) ? apq : apkk;
    const uint4* Wpk  = wpk + (size_t)z * 131072;
    const float* bias = (z == 0) ? bq : (z == 1) ? bk : bv;
    uint4* Opk = (z == 0) ? qpk : (z == 1) ? kpk : vpk;
    gemm_core(Apk, Wpk, bias, nullptr, (z == 0) ? qp : nullptr, Opk,
              z + 2, blockIdx.y, blockIdx.x, smu);
}

// single-config GEMM (final o-projection, mode 1)
__global__ __launch_bounds__(256, 2)
void gemm_f16_kernel(const uint4* __restrict__ Apk, const uint4* __restrict__ Wpk,
                     const float* __restrict__ bias, const float* __restrict__ R,
                     float* __restrict__ C, uint4* __restrict__ Opk, int mode)
{
    extern __shared__ uint4 smu[];
    gemm_core(Apk, Wpk, bias, R, C, Opk, mode, blockIdx.y, blockIdx.x, smu);
}

// ===========================================================================
// Attention v5 (unchanged, passing at rel_err 3.589e-4).
// ===========================================================================
static constexpr int ATT5_SMEM_BYTES = 5120 * 16 + 128 * 4;   // 82432

__global__ __launch_bounds__(256, 2)
void attn5_kernel(const uint4* __restrict__ qpk, const float* __restrict__ qe,
                  const uint4* __restrict__ kpk, const uint4* __restrict__ vpk,
                  float* __restrict__ x)
{
    extern __shared__ uint4 smu[];
    const uint4* Qs = smu;
    float* lrow2 = (float*)(smu + 5120);
    float* stg   = (float*)(smu + 3072);

    const int b    = blockIdx.z;
    const int h    = blockIdx.y;
    const int tile = blockIdx.x;
    const int tid  = threadIdx.x;
    const int lane = tid & 31;
    const int w    = tid >> 5;
    const int wr   = w & 3;
    const int wc   = w >> 2;
    const int g    = lane >> 2, t = lane & 3;

    const uint4* qsrc  = qpk + (((size_t)(b * 16 + tile) * 8 + h) << 10);
    const uint4* kbase = kpk + (((size_t)(b * 8 + h)) << 15);
    const uint4* vbase = vpk + (((size_t)(b * 8 + h)) << 15);
    const float* qeb = qe + ((size_t)(b * CNQ + tile * 64)) * CD + h * CDH;
    float*       xb  = x  + ((size_t)(b * CNQ + tile * 64)) * CD + h * CDH;

    const uint32_t sb = smem_u32(smu);

#pragma unroll
    for (int u = 0; u < 4; ++u)
        cpasync16(sb + (tid + u * 256) * 16, qsrc + tid + u * 256);
#pragma unroll
    for (int u = 0; u < 4; ++u)
        cpasync16(sb + (1024 + tid + u * 256) * 16, kbase + tid + u * 256);
#pragma unroll
    for (int u = 0; u < 4; ++u)
        cpasync16(sb + (3072 + tid + u * 256) * 16, vbase + tid + u * 256);
    CP_COMMIT();

    if (tid < 128) lrow2[tid] = 0.f;

    float oacc[16][4];
#pragma unroll
    for (int n = 0; n < 16; ++n)
#pragma unroll
        for (int c = 0; c < 4; ++c) oacc[n][c] = 0.f;

    const float scale = 0.03125f;

    CP_WAIT(0);
    __syncthreads();

    for (int kt = 0; kt < 32; ++kt) {
        const int cur = kt & 1;
        if (kt + 1 < 32) {
            const int nxt = 1 - cur;
            const uint4* ks = kbase + ((size_t)(kt + 1) << 10);
            const uint4* vs = vbase + ((size_t)(kt + 1) << 10);
#pragma unroll
            for (int u = 0; u < 4; ++u)
                cpasync16(sb + (1024 + nxt * 1024 + tid + u * 256) * 16, ks + tid + u * 256);
#pragma unroll
            for (int u = 0; u < 4; ++u)
                cpasync16(sb + (3072 + nxt * 1024 + tid + u * 256) * 16, vs + tid + u * 256);
            CP_COMMIT();
        }

        const uint4* Ks = smu + 1024 + cur * 1024;
        const uint4* Vs = smu + 3072 + cur * 1024;

        float sacc[4][4];
#pragma unroll
        for (int n = 0; n < 4; ++n)
#pragma unroll
            for (int c = 0; c < 4; ++c) sacc[n][c] = 0.f;
#pragma unroll
        for (int kc = 0; kc < 8; ++kc) {
            uint4 qf = Qs[(wr * 8 + kc) * 32 + lane];
#pragma unroll
            for (int p = 0; p < 2; ++p) {
                uint4 kf = Ks[((kc * 2 + wc) * 2 + p) * 32 + lane];
                mma16816(sacc[2 * p],     qf, kf.x, kf.y);
                mma16816(sacc[2 * p + 1], qf, kf.z, kf.w);
            }
        }

        float e[4][4];
        float sum0 = 0.f, sum1 = 0.f;
#pragma unroll
        for (int n = 0; n < 4; ++n)
#pragma unroll
            for (int c = 0; c < 4; ++c) {
                e[n][c] = __expf(sacc[n][c] * scale);
                if (c < 2) sum0 += e[n][c]; else sum1 += e[n][c];
            }
        sum0 += __shfl_xor_sync(0xffffffffu, sum0, 1);
        sum0 += __shfl_xor_sync(0xffffffffu, sum0, 2);
        sum1 += __shfl_xor_sync(0xffffffffu, sum1, 1);
        sum1 += __shfl_xor_sync(0xffffffffu, sum1, 2);
        if (t == 0) {
            const int r = wr * 16 + g;
            lrow2[wc * 64 + r]     += sum0;
            lrow2[wc * 64 + r + 8] += sum1;
        }
        uint4 pf[2];
        pf[0].x = f2h2(e[0][0], e[0][1]); pf[0].y = f2h2(e[0][2], e[0][3]);
        pf[0].z = f2h2(e[1][0], e[1][1]); pf[0].w = f2h2(e[1][2], e[1][3]);
        pf[1].x = f2h2(e[2][0], e[2][1]); pf[1].y = f2h2(e[2][2], e[2][3]);
        pf[1].z = f2h2(e[3][0], e[3][1]); pf[1].w = f2h2(e[3][2], e[3][3]);

#pragma unroll
        for (int J = 0; J < 2; ++J) {
            const int jc = wc * 2 + J;
#pragma unroll
            for (int wcd = 0; wcd < 2; ++wcd)
#pragma unroll
                for (int p = 0; p < 4; ++p) {
                    uint4 vf = Vs[((jc * 2 + wcd) * 4 + p) * 32 + lane];
                    const int n = wcd * 8 + p * 2;
                    mma16816(oacc[n],     pf[J], vf.x, vf.y);
                    mma16816(oacc[n + 1], pf[J], vf.z, vf.w);
                }
        }

        CP_WAIT(0);
        __syncthreads();
    }

    {
        const int r = wr * 16 + g;
#pragma unroll
        for (int n = (1 - wc) * 8; n < (1 - wc) * 8 + 8; ++n) {
            const int d = n * 8 + 2 * t;
            stg[r * 128 + d]           = oacc[n][0];
            stg[r * 128 + d + 1]       = oacc[n][1];
            stg[(r + 8) * 128 + d]     = oacc[n][2];
            stg[(r + 8) * 128 + d + 1] = oacc[n][3];
        }
    }
    __syncthreads();
    {
        const int r = wr * 16 + g;
        const float inv0 = 1.f / (lrow2[r] + lrow2[64 + r]);
        const float inv8 = 1.f / (lrow2[r + 8] + lrow2[64 + r + 8]);
#pragma unroll
        for (int n = wc * 8; n < wc * 8 + 8; ++n) {
            const int d = n * 8 + 2 * t;
            float2 q0 = *(const float2*)(qeb + (size_t)r * CD + d);
            float2 q8 = *(const float2*)(qeb + (size_t)(r + 8) * CD + d);
            float2 o0, o8;
            o0.x = fmaf(oacc[n][0] + stg[r * 128 + d],           inv0, q0.x);
            o0.y = fmaf(oacc[n][1] + stg[r * 128 + d + 1],       inv0, q0.y);
            o8.x = fmaf(oacc[n][2] + stg[(r + 8) * 128 + d],     inv8, q8.x);
            o8.y = fmaf(oacc[n][3] + stg[(r + 8) * 128 + d + 1], inv8, q8.y);
            *(float2*)(xb + (size_t)r * CD + d)       = o0;
            *(float2*)(xb + (size_t)(r + 8) * CD + d) = o8;
        }
    }
}

// ===========================================================================
// LN (single row) — used for LN1.
// ===========================================================================
__global__ __launch_bounds__(256)
void ln_kernel(const float* __restrict__ in, float* __restrict__ out,
               const float* __restrict__ g, const float* __restrict__ bta)
{
    __shared__ float red_s[8], red_s2[8];
    __shared__ float mu_s, rs_s;
    const int row = blockIdx.x;
    const int tid = threadIdx.x;
    const float* rp = in + (size_t)row * 1024;

    float4 xv = *(const float4*)(rp + tid * 4);
    float s  = xv.x + xv.y + xv.z + xv.w;
    float s2 = xv.x * xv.x + xv.y * xv.y + xv.z * xv.z + xv.w * xv.w;
#pragma unroll
    for (int off = 16; off >= 1; off >>= 1) {
        s  += __shfl_xor_sync(0xffffffffu, s,  off);
        s2 += __shfl_xor_sync(0xffffffffu, s2, off);
    }
    if ((tid & 31) == 0) { red_s[tid >> 5] = s; red_s2[tid >> 5] = s2; }
    __syncthreads();
    if (tid == 0) {
        float a = 0.f, a2 = 0.f;
#pragma unroll
        for (int wq = 0; wq < 8; ++wq) { a += red_s[wq]; a2 += red_s2[wq]; }
        const float mu  = a * (1.f / 1024.f);
        const float var = a2 * (1.f / 1024.f) - mu * mu;
        mu_s = mu;
        rs_s = rsqrtf(var + 1e-5f);
    }
    __syncthreads();
    const float mu = mu_s, rs = rs_s;
    float4 gv = *(const float4*)(g + tid * 4);
    float4 bv = *(const float4*)(bta + tid * 4);
    float4 ov;
    ov.x = (xv.x - mu) * rs * gv.x + bv.x;
    ov.y = (xv.y - mu) * rs * gv.y + bv.y;
    ov.z = (xv.z - mu) * rs * gv.z + bv.z;
    ov.w = (xv.w - mu) * rs * gv.w + bv.w;
    *(float4*)(out + (size_t)row * 1024 + tid * 4) = ov;
}

// ===========================================================================
// LN0 fused with A-frag packing: 16 rows per block (512 threads, 1 warp/row).
// Writes fp32 normalized rows AND the rowtile's packed A-frags.
// ===========================================================================
__global__ __launch_bounds__(512)
void ln16_pack_kernel(const float* __restrict__ in, float* __restrict__ out,
                      const float* __restrict__ g, const float* __restrict__ bta,
                      uint4* __restrict__ apk)
{
    __shared__ __half2 sh[16][520];    // 16 rows x 512 half2 (+8 pad)
    const int w    = threadIdx.x >> 5;
    const int lane = threadIdx.x & 31;
    const int row  = blockIdx.x * 16 + w;
    const float* rp = in + (size_t)row * 1024;

    float4 xv[8];
    float s = 0.f, s2 = 0.f;
#pragma unroll
    for (int u = 0; u < 8; ++u) {
        xv[u] = ((const float4*)rp)[u * 32 + lane];
        s  += xv[u].x + xv[u].y + xv[u].z + xv[u].w;
        s2 += xv[u].x * xv[u].x + xv[u].y * xv[u].y
            + xv[u].z * xv[u].z + xv[u].w * xv[u].w;
    }
#pragma unroll
    for (int off = 16; off >= 1; off >>= 1) {
        s  += __shfl_xor_sync(0xffffffffu, s,  off);
        s2 += __shfl_xor_sync(0xffffffffu, s2, off);
    }
    const float mu = s * (1.f / 1024.f);
    const float rs = rsqrtf(s2 * (1.f / 1024.f) - mu * mu + 1e-5f);

#pragma unroll
    for (int u = 0; u < 8; ++u) {
        const int fi = u * 32 + lane;          // float4 index in row
        float4 gv = ((const float4*)g)[fi];
        float4 bv = ((const float4*)bta)[fi];
        float4 ov;
        ov.x = (xv[u].x - mu) * rs * gv.x + bv.x;
        ov.y = (xv[u].y - mu) * rs * gv.y + bv.y;
        ov.z = (xv[u].z - mu) * rs * gv.z + bv.z;
        ov.w = (xv[u].w - mu) * rs * gv.w + bv.w;
        ((float4*)(out + (size_t)row * 1024))[fi] = ov;
        sh[w][fi * 2]     = __floats2half2_rn(ov.x, ov.y);
        sh[w][fi * 2 + 1] = __floats2half2_rn(ov.z, ov.w);
    }
    __syncthreads();

    // emit this rowtile's A-frags: [rt][kc64][lane32]
#pragma unroll
    for (int i = 0; i < 4; ++i) {
        const int f  = threadIdx.x + i * 512;      // 0..2047
        const int ln = f & 31, kc = f >> 5;
        const int gg = ln >> 2, tt = ln & 3;
        uint4 o;
        o.x = *(uint32_t*)&sh[gg][kc * 8 + tt];
        o.y = *(uint32_t*)&sh[gg + 8][kc * 8 + tt];
        o.z = *(uint32_t*)&sh[gg][kc * 8 + tt + 4];
        o.w = *(uint32_t*)&sh[gg + 8][kc * 8 + tt + 4];
        apk[((size_t)blockIdx.x * 64 + kc) * 32 + ln] = o;
    }
}

// ===========================================================================
extern "C" void kernel_launch(void* const* d_in, const int* in_sizes, int n_in,
                              void* d_out, int out_size)
{
    const float* Q  = (const float*)d_in[0];
    const float* K  = (const float*)d_in[1];
    const float* Wq = (const float*)d_in[2];
    const float* bq = (const float*)d_in[3];
    const float* Wk = (const float*)d_in[4];
    const float* bk = (const float*)d_in[5];
    const float* Wv = (const float*)d_in[6];
    const float* bv = (const float*)d_in[7];
    const float* Wo = (const float*)d_in[8];
    const float* bo = (const float*)d_in[9];
    const float* g0 = (const float*)d_in[10];
    const float* b0 = (const float*)d_in[11];
    const float* g1 = (const float*)d_in[12];
    const float* b1 = (const float*)d_in[13];
    float* out = (float*)d_out;

    float *qp, *xp, *yp;
    uint4 *apq, *apk, *wpk, *qpk, *kpk, *vpk;
    cudaGetSymbolAddress((void**)&qp,  g_q);
    cudaGetSymbolAddress((void**)&xp,  g_x);
    cudaGetSymbolAddress((void**)&yp,  g_y);
    cudaGetSymbolAddress((void**)&apq, g_apq);
    cudaGetSymbolAddress((void**)&apk, g_apk);
    cudaGetSymbolAddress((void**)&wpk, g_wpk);
    cudaGetSymbolAddress((void**)&qpk, g_qpk);
    cudaGetSymbolAddress((void**)&kpk, g_kpk);
    cudaGetSymbolAddress((void**)&vpk, g_vpk);

    cudaFuncSetAttribute(gemm_proj_kernel,
                         cudaFuncAttributeMaxDynamicSharedMemorySize, G16_SMEM_BYTES);
    cudaFuncSetAttribute(gemm_f16_kernel,
                         cudaFuncAttributeMaxDynamicSharedMemorySize, G16_SMEM_BYTES);
    cudaFuncSetAttribute(attn5_kernel,
                         cudaFuncAttributeMaxDynamicSharedMemorySize, ATT5_SMEM_BYTES);

    // 1) pack weights (one launch)
    pack_w_all_kernel<<<2048, 256>>>(Wq, Wk, Wv, Wo, wpk);
    // 2) pack A operands: Q + K (one launch)
    pack_a_all_kernel<<<12288, 256>>>(Q, K, apq, apk);
    // 3) q/k/v projections with fused attn packing (one launch)
    gemm_proj_kernel<<<dim3(8, 128, 3), 256, G16_SMEM_BYTES>>>(
        apq, apk, wpk, bq, bk, bv, qp, qpk, kpk, vpk);
    // 4) attention + residual
    attn5_kernel<<<dim3(16, CH, CB), 256, ATT5_SMEM_BYTES>>>(qpk, qp, kpk, vpk, xp);
    // 5) LN0 + pack A(x) fused (in place fp32 + packed A-frags)
    ln16_pack_kernel<<<512, 512>>>(xp, xp, g0, b0, apq);
    // 6) y = x + relu(x @ Wo + bo)
    gemm_f16_kernel<<<dim3(8, 64), 256, G16_SMEM_BYTES>>>(
        apq, wpk + 3 * 131072, bo, xp, yp, nullptr, 1);
    // 7) LN1 -> out
    ln_kernel<<<CB * CNQ, 256>>>(yp, out, g1, b1);
}